// round 1
// baseline (speedup 1.0000x reference)
#include <cuda_runtime.h>
#include <math.h>

#define B_N 2
#define S_N 2048
#define HID_N 2048
#define H_N 16
#define KV_N 4
#define QKB_N 64
#define VB_N 64

// Scratch (allocation-free rule: __device__ globals). ~41 MB total.
__device__ float g_qb[(size_t)B_N * S_N * H_N * QKB_N];   // tanh(x@Wq)   [B,S,H,64]
__device__ float g_kb[(size_t)B_N * S_N * KV_N * QKB_N];  // tanh(x@Wk)   [B,S,KV,64]
__device__ float g_vp[(size_t)B_N * S_N * KV_N * VB_N];   // sigm(x@Wv)   [B,S,KV,64]
__device__ float g_ob[(size_t)B_N * S_N * H_N * VB_N];    // out_bits     [B,S,H,64]

// ---------------------------------------------------------------------------
// GEMM: C[M,N] = epi(A[M,K] @ B[K,N]).  128x128 tile, BK=8, 256 threads,
// 8x8 per-thread microtile. EPI: 0=none, 1=tanh, 2=sigmoid.
// M,N multiples of 128; K multiple of 8.
// ---------------------------------------------------------------------------
template <int EPI>
__global__ __launch_bounds__(256)
void gemm_kernel(const float* __restrict__ A, const float* __restrict__ Bm,
                 float* __restrict__ C, int M, int N, int K) {
  __shared__ float As[8][128];  // [k][m]
  __shared__ float Bs[8][128];  // [k][n]
  const int tid = threadIdx.x;
  const int tx = tid & 15;
  const int ty = tid >> 4;
  const int m0 = blockIdx.y * 128;
  const int n0 = blockIdx.x * 128;

  float acc[8][8];
#pragma unroll
  for (int i = 0; i < 8; ++i)
#pragma unroll
    for (int j = 0; j < 8; ++j) acc[i][j] = 0.f;

  const int ar = tid >> 1;          // 0..127 (A row in tile)
  const int ac = (tid & 1) * 4;     // 0 or 4 (A col in tile)
  const int br = tid >> 5;          // 0..7   (B row in tile)
  const int bc = (tid & 31) * 4;    // 0..124 (B col in tile)

  const float* Aptr = A + (size_t)(m0 + ar) * K + ac;
  const float* Bptr = Bm + (size_t)br * N + n0 + bc;

  for (int k0 = 0; k0 < K; k0 += 8) {
    float4 av = *(const float4*)(Aptr + k0);
    float4 bv = *(const float4*)(Bptr + (size_t)k0 * N);
    As[ac + 0][ar] = av.x;
    As[ac + 1][ar] = av.y;
    As[ac + 2][ar] = av.z;
    As[ac + 3][ar] = av.w;
    *(float4*)&Bs[br][bc] = bv;
    __syncthreads();
#pragma unroll
    for (int kk = 0; kk < 8; ++kk) {
      float a[8], b[8];
      *(float4*)&a[0] = *(const float4*)&As[kk][ty * 8];
      *(float4*)&a[4] = *(const float4*)&As[kk][ty * 8 + 4];
      *(float4*)&b[0] = *(const float4*)&Bs[kk][tx * 8];
      *(float4*)&b[4] = *(const float4*)&Bs[kk][tx * 8 + 4];
#pragma unroll
      for (int i = 0; i < 8; ++i)
#pragma unroll
        for (int j = 0; j < 8; ++j) acc[i][j] = fmaf(a[i], b[j], acc[i][j]);
    }
    __syncthreads();
  }

#pragma unroll
  for (int i = 0; i < 8; ++i) {
    float* crow = C + (size_t)(m0 + ty * 8 + i) * N + n0 + tx * 8;
#pragma unroll
    for (int j = 0; j < 8; ++j) {
      float v = acc[i][j];
      if (EPI == 1) v = tanhf(v);
      else if (EPI == 2) v = 1.0f / (1.0f + expf(-v));
      crow[j] = v;
    }
  }
}

// ---------------------------------------------------------------------------
// Flash attention over precomputed qb/kb/vp. One CTA per (64-query tile, h, b).
// 256 threads, 4x4 microtiles over a 64x64 score tile, online softmax with
// width-16 shuffle row reductions. Fused emb0/emb1 affine epilogue -> g_ob.
// ---------------------------------------------------------------------------
__global__ __launch_bounds__(256)
void attn_kernel(const int* __restrict__ amask,
                 const float* __restrict__ emb0,
                 const float* __restrict__ emb1) {
  extern __shared__ float sm[];
  float* Qs = sm;              // [64][64]  (broadcast reads -> no pad needed)
  float* Ps = Qs + 64 * 64;    // [64][64]
  float* Ks = Ps + 64 * 64;    // [64][65]  (padded: strided reads)
  float* Vs = Ks + 64 * 65;    // [64][65]
  int*   Ms = (int*)(Vs + 64 * 65);  // [64] attention_mask tile

  const int qt = blockIdx.x;
  const int h  = blockIdx.y;
  const int b  = blockIdx.z;
  const int kv = h >> 2;  // H/KV = 4, jnp.repeat -> contiguous groups
  const int tid = threadIdx.x;
  const int tx = tid & 15;
  const int ty = tid >> 4;
  const int q0 = qt * 64;

  for (int i = tid; i < 64 * 64; i += 256) {
    int r = i >> 6, d = i & 63;
    Qs[r * 64 + d] = g_qb[(((size_t)b * S_N + q0 + r) * H_N + h) * QKB_N + d];
  }

  float acc[4][4];
  float mrow[4], lrow[4];
#pragma unroll
  for (int i = 0; i < 4; ++i) {
    mrow[i] = -3.402823466e38f;
    lrow[i] = 0.f;
#pragma unroll
    for (int j = 0; j < 4; ++j) acc[i][j] = 0.f;
  }

  for (int kt = 0; kt <= qt; ++kt) {
    const int k0 = kt * 64;
    __syncthreads();  // prior PV reads of Ks/Vs/Ps done (also covers Qs load)
    for (int i = tid; i < 64 * 64; i += 256) {
      int r = i >> 6, d = i & 63;
      size_t base = ((size_t)b * S_N + k0 + r) * KV_N + kv;
      Ks[r * 65 + d] = g_kb[base * QKB_N + d];
      Vs[r * 65 + d] = g_vp[base * VB_N + d];
    }
    if (tid < 64) Ms[tid] = amask[b * S_N + k0 + tid];
    __syncthreads();

    // S = Q @ K^T (this thread: rows ty*4.., cols tx*4..)
    float s[4][4];
#pragma unroll
    for (int i = 0; i < 4; ++i)
#pragma unroll
      for (int j = 0; j < 4; ++j) s[i][j] = 0.f;
    for (int d = 0; d < 64; ++d) {
      float qr[4], kr[4];
#pragma unroll
      for (int i = 0; i < 4; ++i) qr[i] = Qs[(ty * 4 + i) * 64 + d];
#pragma unroll
      for (int j = 0; j < 4; ++j) kr[j] = Ks[(tx * 4 + j) * 65 + d];
#pragma unroll
      for (int i = 0; i < 4; ++i)
#pragma unroll
        for (int j = 0; j < 4; ++j) s[i][j] = fmaf(qr[i], kr[j], s[i][j]);
    }

    // scale + causal/padding mask (reference uses finfo.min, exp underflows to 0)
#pragma unroll
    for (int i = 0; i < 4; ++i) {
      int qi = q0 + ty * 4 + i;
#pragma unroll
      for (int j = 0; j < 4; ++j) {
        int ki = k0 + tx * 4 + j;
        float v = s[i][j] * (1.0f / 64.0f);
        if (ki > qi || Ms[tx * 4 + j] == 0) v = -3.402823466e38f;
        s[i][j] = v;
      }
    }

    // online softmax; row groups = 16 threads with the same ty = one half-warp
#pragma unroll
    for (int i = 0; i < 4; ++i) {
      float rm = s[i][0];
#pragma unroll
      for (int j = 1; j < 4; ++j) rm = fmaxf(rm, s[i][j]);
#pragma unroll
      for (int o = 8; o > 0; o >>= 1)
        rm = fmaxf(rm, __shfl_xor_sync(0xffffffffu, rm, o, 16));
      float mnew = fmaxf(mrow[i], rm);
      float scale = __expf(mrow[i] - mnew);
      mrow[i] = mnew;
      float rs = 0.f;
#pragma unroll
      for (int j = 0; j < 4; ++j) {
        float p = __expf(s[i][j] - mnew);
        Ps[(ty * 4 + i) * 64 + tx * 4 + j] = p;
        rs += p;
      }
#pragma unroll
      for (int o = 8; o > 0; o >>= 1)
        rs += __shfl_xor_sync(0xffffffffu, rs, o, 16);
      lrow[i] = lrow[i] * scale + rs;
#pragma unroll
      for (int j = 0; j < 4; ++j) acc[i][j] *= scale;
    }
    __syncthreads();  // Ps visible

    // acc += P @ V
    for (int kk = 0; kk < 64; ++kk) {
      float pr[4], vr[4];
#pragma unroll
      for (int i = 0; i < 4; ++i) pr[i] = Ps[(ty * 4 + i) * 64 + kk];
#pragma unroll
      for (int j = 0; j < 4; ++j) vr[j] = Vs[kk * 65 + tx * 4 + j];
#pragma unroll
      for (int i = 0; i < 4; ++i)
#pragma unroll
        for (int j = 0; j < 4; ++j) acc[i][j] = fmaf(pr[i], vr[j], acc[i][j]);
    }
  }

  // epilogue: ctx = acc/l; out_bits = emb0 + ctx*(emb1-emb0)
#pragma unroll
  for (int i = 0; i < 4; ++i) {
    int qi = q0 + ty * 4 + i;
    float inv_l = 1.0f / lrow[i];
#pragma unroll
    for (int j = 0; j < 4; ++j) {
      int vc = tx * 4 + j;
      float ctx = acc[i][j] * inv_l;
      float e0 = emb0[h * VB_N + vc];
      float e1 = emb1[h * VB_N + vc];
      g_ob[(((size_t)b * S_N + qi) * H_N + h) * VB_N + vc] = e0 + ctx * (e1 - e0);
    }
  }
}

// ---------------------------------------------------------------------------
extern "C" void kernel_launch(void* const* d_in, const int* in_sizes, int n_in,
                              void* d_out, int out_size) {
  const float* x  = (const float*)d_in[0];
  const int*   am = (const int*)d_in[1];
  const float* Wq = (const float*)d_in[2];
  const float* Wk = (const float*)d_in[3];
  const float* Wv = (const float*)d_in[4];
  const float* Wo = (const float*)d_in[5];
  const float* e0 = (const float*)d_in[6];
  const float* e1 = (const float*)d_in[7];
  float* out = (float*)d_out;

  float *qb, *kb, *vp, *ob;
  cudaGetSymbolAddress((void**)&qb, g_qb);
  cudaGetSymbolAddress((void**)&kb, g_kb);
  cudaGetSymbolAddress((void**)&vp, g_vp);
  cudaGetSymbolAddress((void**)&ob, g_ob);

  const int M = B_N * S_N;  // 4096
  dim3 blk(256);

  // projections (+ soft binarization epilogues)
  gemm_kernel<1><<<dim3((H_N * QKB_N) / 128, M / 128), blk>>>(x, Wq, qb, M, H_N * QKB_N, HID_N);
  gemm_kernel<1><<<dim3((KV_N * QKB_N) / 128, M / 128), blk>>>(x, Wk, kb, M, KV_N * QKB_N, HID_N);
  gemm_kernel<2><<<dim3((KV_N * VB_N) / 128, M / 128), blk>>>(x, Wv, vp, M, KV_N * VB_N, HID_N);

  // flash attention + out_bits epilogue
  size_t asmem = (size_t)(2 * 64 * 64 + 2 * 64 * 65) * sizeof(float) + 64 * sizeof(int);
  cudaFuncSetAttribute(attn_kernel, cudaFuncAttributeMaxDynamicSharedMemorySize, (int)asmem);
  attn_kernel<<<dim3(S_N / 64, H_N, B_N), blk, asmem>>>(am, e0, e1);

  // output projection
  gemm_kernel<0><<<dim3(HID_N / 128, M / 128), blk>>>(ob, Wo, out, M, HID_N, H_N * VB_N);
}

// round 4
// speedup vs baseline: 1.7873x; 1.7873x over previous
#include <cuda_runtime.h>
#include <stdint.h>
#include <math.h>

#define B_N 2
#define S_N 2048
#define HID_N 2048
#define H_N 16
#define KV_N 4
#define QKB_N 64
#define VB_N 64
#define MTOT (B_N * S_N)

// ---- scratch (__device__ globals: allocation-free rule) ----
__device__ float g_qb[(size_t)MTOT * H_N * QKB_N];
__device__ float g_kb[(size_t)MTOT * KV_N * QKB_N];
__device__ float g_vp[(size_t)MTOT * KV_N * VB_N];
__device__ float g_obd[(size_t)MTOT * H_N * VB_N];
__device__ float g_cvec[HID_N];

// ---- helpers ----
__device__ __forceinline__ uint32_t smem_u32(const void* p) {
  return (uint32_t)__cvta_generic_to_shared(p);
}

__device__ __forceinline__ void cp16(uint32_t dst, const void* src) {
  asm volatile("cp.async.cg.shared.global [%0], [%1], 16;"
               : : "r"(dst), "l"(src) : "memory");
}

__device__ __forceinline__ void cp_commit() {
  asm volatile("cp.async.commit_group;" : : : "memory");
}

__device__ __forceinline__ void cp_wait0() {
  asm volatile("cp.async.wait_group 0;" : : : "memory");
}

__device__ __forceinline__ uint32_t f2tf32(float v) {
  uint32_t r;
  asm("cvt.rna.tf32.f32 %0, %1;" : "=r"(r) : "f"(v));
  return r;
}

__device__ __forceinline__ void mma_tf32(float* d, const uint32_t* a, const uint32_t* b) {
  asm volatile(
    "mma.sync.aligned.m16n8k8.row.col.f32.tf32.tf32.f32 "
    "{%0,%1,%2,%3}, {%4,%5,%6,%7}, {%8,%9}, {%0,%1,%2,%3};"
    : "+f"(d[0]), "+f"(d[1]), "+f"(d[2]), "+f"(d[3])
    : "r"(a[0]), "r"(a[1]), "r"(a[2]), "r"(a[3]), "r"(b[0]), "r"(b[1]));
}

// ---- cvec[n] = sum_k 0.5*(e0[k]+e1[k]) * Wo[k][n] (exact fp32) ----
__global__ void cvec_kernel(const float* __restrict__ e0, const float* __restrict__ e1,
                            const float* __restrict__ Wo) {
  int n = blockIdx.x * blockDim.x + threadIdx.x;
  if (n < HID_N) {
    float s = 0.f;
    for (int k = 0; k < H_N * VB_N; ++k) {
      s = fmaf(0.5f * (e0[k] + e1[k]), Wo[(size_t)k * HID_N + n], s);
    }
    g_cvec[n] = s;
  }
}

// ---------------------------------------------------------------------------
// TF32 tensor-core GEMM: C[M,N](fp32) = epi(A[M,K] @ B[K,N]), fp32 in/out.
// 128x128x16 tile, 256 threads (8 warps, 4m x 2n), mma.m16n8k8.tf32,
// cp.async double buffer, conflict-free scalar LDS operand fetch.
// EPI: 0=none, 1=tanh, 2=sigmoid, 3=add cvec[col].
// ---------------------------------------------------------------------------
#define LDA 20    // floats per A smem row (16 + 4 pad)  -> banks conflict-free
#define LDB 136   // floats per B smem row (128 + 8 pad) -> banks conflict-free

__device__ __forceinline__ void gemm_prefetch(
    const float* __restrict__ A, const float* __restrict__ Bm,
    float* AsBuf, float* BsBuf, int tid, int m0, int n0, int kt, int K, int N) {
  {
    int c0 = tid;
    int row = c0 >> 2, kc = (c0 & 3) * 4;
    cp16(smem_u32(AsBuf + row * LDA + kc), A + (size_t)(m0 + row) * K + kt * 16 + kc);
    int c1 = tid + 256;
    int row1 = c1 >> 2, kc1 = (c1 & 3) * 4;
    cp16(smem_u32(AsBuf + row1 * LDA + kc1), A + (size_t)(m0 + row1) * K + kt * 16 + kc1);
  }
  {
    int c0 = tid;
    int row = c0 >> 5, nc = (c0 & 31) * 4;
    cp16(smem_u32(BsBuf + row * LDB + nc), Bm + (size_t)(kt * 16 + row) * N + n0 + nc);
    int c1 = tid + 256;
    int row1 = c1 >> 5, nc1 = (c1 & 31) * 4;
    cp16(smem_u32(BsBuf + row1 * LDB + nc1), Bm + (size_t)(kt * 16 + row1) * N + n0 + nc1);
  }
}

template <int EPI>
__global__ __launch_bounds__(256)
void gemm_tf32(const float* __restrict__ A, const float* __restrict__ Bm,
               float* __restrict__ C, int M, int N, int K,
               const float* __restrict__ cvec) {
  __shared__ float As[2][128 * LDA];
  __shared__ float Bs[2][16 * LDB];
  const int tid = threadIdx.x;
  const int wid = tid >> 5;
  const int lane = tid & 31;
  const int wm = wid & 3;
  const int wn = wid >> 2;
  const int m0 = blockIdx.y * 128;
  const int n0 = blockIdx.x * 128;
  const int lg = lane >> 2;   // group id 0..7
  const int lt = lane & 3;    // thread-in-group 0..3

  float acc[2][8][4];
#pragma unroll
  for (int i = 0; i < 2; ++i) {
#pragma unroll
    for (int j = 0; j < 8; ++j) {
#pragma unroll
      for (int t = 0; t < 4; ++t) { acc[i][j][t] = 0.f; }
    }
  }

  const int KT = K / 16;
  gemm_prefetch(A, Bm, As[0], Bs[0], tid, m0, n0, 0, K, N);
  cp_commit();

  for (int kt = 0; kt < KT; ++kt) {
    const int buf = kt & 1;
    cp_wait0();
    __syncthreads();
    if (kt + 1 < KT) {
      gemm_prefetch(A, Bm, As[buf ^ 1], Bs[buf ^ 1], tid, m0, n0, kt + 1, K, N);
      cp_commit();
    }

#pragma unroll
    for (int ks = 0; ks < 2; ++ks) {
      uint32_t a[2][4];
      uint32_t b[8][2];
#pragma unroll
      for (int mi = 0; mi < 2; ++mi) {
        const float* ab = &As[buf][(wm * 32 + mi * 16 + lg) * LDA + ks * 8 + lt];
        a[mi][0] = f2tf32(ab[0]);
        a[mi][1] = f2tf32(ab[8 * LDA]);
        a[mi][2] = f2tf32(ab[4]);
        a[mi][3] = f2tf32(ab[8 * LDA + 4]);
      }
#pragma unroll
      for (int nj = 0; nj < 8; ++nj) {
        const float* bb = &Bs[buf][(ks * 8 + lt) * LDB + wn * 64 + nj * 8 + lg];
        b[nj][0] = f2tf32(bb[0]);
        b[nj][1] = f2tf32(bb[4 * LDB]);
      }
#pragma unroll
      for (int mi = 0; mi < 2; ++mi) {
#pragma unroll
        for (int nj = 0; nj < 8; ++nj) { mma_tf32(acc[mi][nj], a[mi], b[nj]); }
      }
    }
    __syncthreads();
  }

#pragma unroll
  for (int mi = 0; mi < 2; ++mi) {
    int r0 = m0 + wm * 32 + mi * 16 + lg;
#pragma unroll
    for (int nj = 0; nj < 8; ++nj) {
      int col = n0 + wn * 64 + nj * 8 + lt * 2;
#pragma unroll
      for (int half = 0; half < 2; ++half) {
        int row = r0 + half * 8;
        float v0 = acc[mi][nj][half * 2 + 0];
        float v1 = acc[mi][nj][half * 2 + 1];
        if (EPI == 1) {
          v0 = tanhf(v0); v1 = tanhf(v1);
        } else if (EPI == 2) {
          v0 = 1.f / (1.f + __expf(-v0)); v1 = 1.f / (1.f + __expf(-v1));
        } else if (EPI == 3) {
          v0 += cvec[col]; v1 += cvec[col + 1];
        }
        float2 v2 = make_float2(v0, v1);
        *(float2*)&C[(size_t)row * N + col] = v2;
      }
    }
  }
}

// ---------------------------------------------------------------------------
// Flash attention: 128 queries x 64 keys per tile, 256 threads, 8x4 microtile,
// d-major (transposed) smem tiles so operand reads are LDS.128.
// Epilogue writes centered fp32 out-bits: (ctx-0.5)*(e1-e0).
// ---------------------------------------------------------------------------
#define LDQ 132
#define LDK 68

__global__ __launch_bounds__(256)
void attn_kernel(const int* __restrict__ amask,
                 const float* __restrict__ emb0,
                 const float* __restrict__ emb1) {
  extern __shared__ float smn[];
  float* Qt = smn;                  // [64 d][LDQ]    Qt[d][qrow]
  float* Pt = Qt + 64 * LDQ;        // [64 kcol][LDQ] Pt[kcol][qrow]
  float* Ks = Pt + 64 * LDQ;        // [64 d][LDK]    Ks[d][krow]
  float* Vs = Ks + 64 * LDK;        // [64 krow][LDK] Vs[krow][vcol]
  int*   Ms = (int*)(Vs + 64 * LDK);

  const int qt = blockIdx.x;
  const int h  = blockIdx.y;
  const int b  = blockIdx.z;
  const int kv = h >> 2;
  const int tid = threadIdx.x;
  const int tx = tid & 15;
  const int ty = tid >> 4;
  const int q0 = qt * 128;

#pragma unroll
  for (int it = 0; it < 8; ++it) {
    int c = tid + it * 256;
    int qrow = c >> 4;
    int d0 = (c & 15) * 4;
    float4 v = *(const float4*)&g_qb[(((size_t)b * S_N + q0 + qrow) * H_N + h) * QKB_N + d0];
    Qt[(d0 + 0) * LDQ + qrow] = v.x;
    Qt[(d0 + 1) * LDQ + qrow] = v.y;
    Qt[(d0 + 2) * LDQ + qrow] = v.z;
    Qt[(d0 + 3) * LDQ + qrow] = v.w;
  }

  float acc[8][4];
  float mrow[8];
  float lrow[8];
#pragma unroll
  for (int i = 0; i < 8; ++i) {
    mrow[i] = -3.402823466e38f;
    lrow[i] = 0.f;
#pragma unroll
    for (int j = 0; j < 4; ++j) { acc[i][j] = 0.f; }
  }

  const int nkt = 2 * qt + 2;
  for (int kt = 0; kt < nkt; ++kt) {
    const int k0 = kt * 64;
    __syncthreads();
#pragma unroll
    for (int it = 0; it < 4; ++it) {
      int c = tid + it * 256;
      int krow = c >> 4;
      int d0 = (c & 15) * 4;
      size_t base = ((size_t)b * S_N + k0 + krow) * KV_N + kv;
      float4 kk = *(const float4*)&g_kb[base * QKB_N + d0];
      Ks[(d0 + 0) * LDK + krow] = kk.x;
      Ks[(d0 + 1) * LDK + krow] = kk.y;
      Ks[(d0 + 2) * LDK + krow] = kk.z;
      Ks[(d0 + 3) * LDK + krow] = kk.w;
      float4 vv = *(const float4*)&g_vp[base * VB_N + d0];
      *(float4*)&Vs[krow * LDK + d0] = vv;
    }
    if (tid < 64) { Ms[tid] = amask[b * S_N + k0 + tid]; }
    __syncthreads();

    float s[8][4];
#pragma unroll
    for (int i = 0; i < 8; ++i) {
#pragma unroll
      for (int j = 0; j < 4; ++j) { s[i][j] = 0.f; }
    }
#pragma unroll 2
    for (int d = 0; d < 64; ++d) {
      float q[8];
      float k4[4];
      *(float4*)&q[0] = *(const float4*)&Qt[d * LDQ + ty * 8];
      *(float4*)&q[4] = *(const float4*)&Qt[d * LDQ + ty * 8 + 4];
      *(float4*)&k4[0] = *(const float4*)&Ks[d * LDK + tx * 4];
#pragma unroll
      for (int i = 0; i < 8; ++i) {
#pragma unroll
        for (int j = 0; j < 4; ++j) { s[i][j] = fmaf(q[i], k4[j], s[i][j]); }
      }
    }

#pragma unroll
    for (int i = 0; i < 8; ++i) {
      int qi = q0 + ty * 8 + i;
#pragma unroll
      for (int j = 0; j < 4; ++j) {
        int ki = k0 + tx * 4 + j;
        float v = s[i][j] * (1.0f / 64.0f);
        if (ki > qi || Ms[tx * 4 + j] == 0) { v = -3.402823466e38f; }
        s[i][j] = v;
      }
    }

#pragma unroll
    for (int i = 0; i < 8; ++i) {
      float rm = fmaxf(fmaxf(s[i][0], s[i][1]), fmaxf(s[i][2], s[i][3]));
#pragma unroll
      for (int o = 8; o > 0; o >>= 1) {
        rm = fmaxf(rm, __shfl_xor_sync(0xffffffffu, rm, o, 16));
      }
      float mnew = fmaxf(mrow[i], rm);
      float scale = __expf(mrow[i] - mnew);
      mrow[i] = mnew;
      float rs = 0.f;
#pragma unroll
      for (int j = 0; j < 4; ++j) {
        float p = __expf(s[i][j] - mnew);
        s[i][j] = p;
        rs += p;
      }
#pragma unroll
      for (int o = 8; o > 0; o >>= 1) {
        rs += __shfl_xor_sync(0xffffffffu, rs, o, 16);
      }
      lrow[i] = lrow[i] * scale + rs;
#pragma unroll
      for (int j = 0; j < 4; ++j) { acc[i][j] *= scale; }
    }

#pragma unroll
    for (int j = 0; j < 4; ++j) {
      float4 p0 = make_float4(s[0][j], s[1][j], s[2][j], s[3][j]);
      float4 p1 = make_float4(s[4][j], s[5][j], s[6][j], s[7][j]);
      *(float4*)&Pt[(tx * 4 + j) * LDQ + ty * 8] = p0;
      *(float4*)&Pt[(tx * 4 + j) * LDQ + ty * 8 + 4] = p1;
    }
    __syncthreads();

#pragma unroll 2
    for (int kk = 0; kk < 64; ++kk) {
      float p[8];
      float v4[4];
      *(float4*)&p[0] = *(const float4*)&Pt[kk * LDQ + ty * 8];
      *(float4*)&p[4] = *(const float4*)&Pt[kk * LDQ + ty * 8 + 4];
      *(float4*)&v4[0] = *(const float4*)&Vs[kk * LDK + tx * 4];
#pragma unroll
      for (int i = 0; i < 8; ++i) {
#pragma unroll
        for (int j = 0; j < 4; ++j) { acc[i][j] = fmaf(p[i], v4[j], acc[i][j]); }
      }
    }
  }

#pragma unroll
  for (int i = 0; i < 8; ++i) {
    int qi = q0 + ty * 8 + i;
    float inv = 1.0f / lrow[i];
#pragma unroll
    for (int j = 0; j < 4; ++j) {
      int vc = tx * 4 + j;
      float ctx = acc[i][j] * inv;
      float diff = emb1[h * VB_N + vc] - emb0[h * VB_N + vc];
      g_obd[(((size_t)b * S_N + qi) * H_N + h) * VB_N + vc] = (ctx - 0.5f) * diff;
    }
  }
}

// ---------------------------------------------------------------------------
extern "C" void kernel_launch(void* const* d_in, const int* in_sizes, int n_in,
                              void* d_out, int out_size) {
  const float* x  = (const float*)d_in[0];
  const int*   am = (const int*)d_in[1];
  const float* Wq = (const float*)d_in[2];
  const float* Wk = (const float*)d_in[3];
  const float* Wv = (const float*)d_in[4];
  const float* Wo = (const float*)d_in[5];
  const float* e0 = (const float*)d_in[6];
  const float* e1 = (const float*)d_in[7];
  float* out = (float*)d_out;

  float* qb;  float* kb;  float* vp;  float* obd;  float* cvec;
  cudaGetSymbolAddress((void**)&qb, g_qb);
  cudaGetSymbolAddress((void**)&kb, g_kb);
  cudaGetSymbolAddress((void**)&vp, g_vp);
  cudaGetSymbolAddress((void**)&obd, g_obd);
  cudaGetSymbolAddress((void**)&cvec, g_cvec);

  const int M = MTOT;

  cvec_kernel<<<HID_N / 256, 256>>>(e0, e1, Wo);

  gemm_tf32<1><<<dim3(H_N * QKB_N / 128, M / 128), 256>>>(x, Wq, qb, M, H_N * QKB_N, HID_N, (const float*)0);
  gemm_tf32<1><<<dim3(KV_N * QKB_N / 128, M / 128), 256>>>(x, Wk, kb, M, KV_N * QKB_N, HID_N, (const float*)0);
  gemm_tf32<2><<<dim3(KV_N * VB_N / 128, M / 128), 256>>>(x, Wv, vp, M, KV_N * VB_N, HID_N, (const float*)0);

  size_t asmem = (size_t)(64 * LDQ + 64 * LDQ + 64 * LDK + 64 * LDK) * sizeof(float) + 64 * sizeof(int);
  cudaFuncSetAttribute(attn_kernel, cudaFuncAttributeMaxDynamicSharedMemorySize, (int)asmem);
  attn_kernel<<<dim3(S_N / 128, H_N, B_N), 256, asmem>>>(am, e0, e1);

  gemm_tf32<3><<<dim3(HID_N / 128, M / 128), 256>>>(obd, Wo, out, M, HID_N, H_N * VB_N, cvec);
}

// round 5
// speedup vs baseline: 3.1055x; 1.7376x over previous
#include <cuda_runtime.h>
#include <stdint.h>
#include <math.h>

#define B_N 2
#define S_N 2048
#define HID_N 2048
#define H_N 16
#define KV_N 4
#define QKB_N 64
#define VB_N 64
#define MTOT (B_N * S_N)

// ---- scratch (__device__ globals: allocation-free rule) ----
__device__ float g_qb[(size_t)MTOT * H_N * QKB_N];
__device__ float g_kb[(size_t)MTOT * KV_N * QKB_N];
__device__ float g_vp[(size_t)MTOT * KV_N * VB_N];
__device__ float g_obd[(size_t)MTOT * H_N * VB_N];
__device__ float g_cvec[HID_N];

// ---- helpers ----
__device__ __forceinline__ uint32_t smem_u32(const void* p) {
  return (uint32_t)__cvta_generic_to_shared(p);
}

__device__ __forceinline__ void cp16(uint32_t dst, const void* src) {
  asm volatile("cp.async.cg.shared.global [%0], [%1], 16;"
               : : "r"(dst), "l"(src) : "memory");
}

__device__ __forceinline__ void cp_commit() {
  asm volatile("cp.async.commit_group;" : : : "memory");
}

__device__ __forceinline__ void cp_wait0() {
  asm volatile("cp.async.wait_group 0;" : : : "memory");
}

__device__ __forceinline__ uint32_t f2tf32(float v) {
  uint32_t r;
  asm("cvt.rna.tf32.f32 %0, %1;" : "=r"(r) : "f"(v));
  return r;
}

__device__ __forceinline__ void mma_tf32(float* d, const uint32_t* a, const uint32_t* b) {
  asm volatile(
    "mma.sync.aligned.m16n8k8.row.col.f32.tf32.tf32.f32 "
    "{%0,%1,%2,%3}, {%4,%5,%6,%7}, {%8,%9}, {%0,%1,%2,%3};"
    : "+f"(d[0]), "+f"(d[1]), "+f"(d[2]), "+f"(d[3])
    : "r"(a[0]), "r"(a[1]), "r"(a[2]), "r"(a[3]), "r"(b[0]), "r"(b[1]));
}

// ---- cvec[n] = sum_k 0.5*(e0[k]+e1[k]) * Wo[k][n] (exact fp32) ----
__global__ void cvec_kernel(const float* __restrict__ e0, const float* __restrict__ e1,
                            const float* __restrict__ Wo) {
  int n = blockIdx.x * blockDim.x + threadIdx.x;
  if (n < HID_N) {
    float s = 0.f;
    for (int k = 0; k < H_N * VB_N; ++k) {
      s = fmaf(0.5f * (e0[k] + e1[k]), Wo[(size_t)k * HID_N + n], s);
    }
    g_cvec[n] = s;
  }
}

// ---------------------------------------------------------------------------
// TF32 tensor-core GEMM body: C[..,N] tile (m0,n0) = epi(A @ B).
// 128x128x16 tile, 256 threads, mma.m16n8k8.
// epi: 0=none, 1=tanh, 2=sigmoid, 3=add cvec[col].
// ---------------------------------------------------------------------------
#define LDA 20
#define LDB 136

__device__ __forceinline__ void gemm_prefetch(
    const float* __restrict__ A, const float* __restrict__ Bm,
    float* AsBuf, float* BsBuf, int tid, int m0, int n0, int kt, int K, int N) {
  {
    int c0 = tid;
    int row = c0 >> 2, kc = (c0 & 3) * 4;
    cp16(smem_u32(AsBuf + row * LDA + kc), A + (size_t)(m0 + row) * K + kt * 16 + kc);
    int c1 = tid + 256;
    int row1 = c1 >> 2, kc1 = (c1 & 3) * 4;
    cp16(smem_u32(AsBuf + row1 * LDA + kc1), A + (size_t)(m0 + row1) * K + kt * 16 + kc1);
  }
  {
    int c0 = tid;
    int row = c0 >> 5, nc = (c0 & 31) * 4;
    cp16(smem_u32(BsBuf + row * LDB + nc), Bm + (size_t)(kt * 16 + row) * N + n0 + nc);
    int c1 = tid + 256;
    int row1 = c1 >> 5, nc1 = (c1 & 31) * 4;
    cp16(smem_u32(BsBuf + row1 * LDB + nc1), Bm + (size_t)(kt * 16 + row1) * N + n0 + nc1);
  }
}

__device__ __forceinline__ void gemm_body(
    const float* __restrict__ A, const float* __restrict__ Bm,
    float* __restrict__ C, int N, int K, int m0, int n0, int epi,
    const float* __restrict__ cvec,
    float* As0, float* As1, float* Bs0, float* Bs1) {
  const int tid = threadIdx.x;
  const int wid = tid >> 5;
  const int lane = tid & 31;
  const int wm = wid & 3;
  const int wn = wid >> 2;
  const int lg = lane >> 2;
  const int lt = lane & 3;

  float acc[2][8][4];
#pragma unroll
  for (int i = 0; i < 2; ++i) {
#pragma unroll
    for (int j = 0; j < 8; ++j) {
#pragma unroll
      for (int t = 0; t < 4; ++t) { acc[i][j][t] = 0.f; }
    }
  }

  const int KT = K / 16;
  gemm_prefetch(A, Bm, As0, Bs0, tid, m0, n0, 0, K, N);
  cp_commit();

  for (int kt = 0; kt < KT; ++kt) {
    float* Asb = (kt & 1) ? As1 : As0;
    float* Bsb = (kt & 1) ? Bs1 : Bs0;
    cp_wait0();
    __syncthreads();
    if (kt + 1 < KT) {
      float* Asn = (kt & 1) ? As0 : As1;
      float* Bsn = (kt & 1) ? Bs0 : Bs1;
      gemm_prefetch(A, Bm, Asn, Bsn, tid, m0, n0, kt + 1, K, N);
      cp_commit();
    }

#pragma unroll
    for (int ks = 0; ks < 2; ++ks) {
      uint32_t a[2][4];
      uint32_t b[8][2];
#pragma unroll
      for (int mi = 0; mi < 2; ++mi) {
        const float* ab = &Asb[(wm * 32 + mi * 16 + lg) * LDA + ks * 8 + lt];
        a[mi][0] = f2tf32(ab[0]);
        a[mi][1] = f2tf32(ab[8 * LDA]);
        a[mi][2] = f2tf32(ab[4]);
        a[mi][3] = f2tf32(ab[8 * LDA + 4]);
      }
#pragma unroll
      for (int nj = 0; nj < 8; ++nj) {
        const float* bb = &Bsb[(ks * 8 + lt) * LDB + wn * 64 + nj * 8 + lg];
        b[nj][0] = f2tf32(bb[0]);
        b[nj][1] = f2tf32(bb[4 * LDB]);
      }
#pragma unroll
      for (int mi = 0; mi < 2; ++mi) {
#pragma unroll
        for (int nj = 0; nj < 8; ++nj) { mma_tf32(acc[mi][nj], a[mi], b[nj]); }
      }
    }
    __syncthreads();
  }

#pragma unroll
  for (int mi = 0; mi < 2; ++mi) {
    int r0 = m0 + wm * 32 + mi * 16 + lg;
#pragma unroll
    for (int nj = 0; nj < 8; ++nj) {
      int col = n0 + wn * 64 + nj * 8 + lt * 2;
#pragma unroll
      for (int half = 0; half < 2; ++half) {
        int row = r0 + half * 8;
        float v0 = acc[mi][nj][half * 2 + 0];
        float v1 = acc[mi][nj][half * 2 + 1];
        if (epi == 1) {
          v0 = tanhf(v0); v1 = tanhf(v1);
        } else if (epi == 2) {
          v0 = 1.f / (1.f + __expf(-v0)); v1 = 1.f / (1.f + __expf(-v1));
        } else if (epi == 3) {
          v0 += cvec[col]; v1 += cvec[col + 1];
        }
        float2 v2 = make_float2(v0, v1);
        *(float2*)&C[(size_t)row * N + col] = v2;
      }
    }
  }
}

// Fused Q/K/V projection: grid.x = 12 column tiles (0-7 Q, 8-9 K, 10-11 V).
__global__ __launch_bounds__(256, 2)
void gemm_qkv(const float* __restrict__ x,
              const float* __restrict__ Wq, const float* __restrict__ Wk,
              const float* __restrict__ Wv,
              float* __restrict__ qb, float* __restrict__ kb, float* __restrict__ vp) {
  __shared__ float As[2][128 * LDA];
  __shared__ float Bs[2][16 * LDB];
  const int xt = blockIdx.x;
  const int m0 = blockIdx.y * 128;
  const float* Bm;
  float* C;
  int N, n0, epi;
  if (xt < 8) {
    Bm = Wq; C = qb; N = H_N * QKB_N; n0 = xt * 128; epi = 1;
  } else if (xt < 10) {
    Bm = Wk; C = kb; N = KV_N * QKB_N; n0 = (xt - 8) * 128; epi = 1;
  } else {
    Bm = Wv; C = vp; N = KV_N * VB_N; n0 = (xt - 10) * 128; epi = 2;
  }
  gemm_body(x, Bm, C, N, HID_N, m0, n0, epi, (const float*)0,
            As[0], As[1], Bs[0], Bs[1]);
}

// Output projection: out = obd @ Wo + cvec
__global__ __launch_bounds__(256, 2)
void gemm_out(const float* __restrict__ obd, const float* __restrict__ Wo,
              float* __restrict__ out, const float* __restrict__ cvec) {
  __shared__ float As[2][128 * LDA];
  __shared__ float Bs[2][16 * LDB];
  gemm_body(obd, Wo, out, HID_N, H_N * VB_N, blockIdx.y * 128, blockIdx.x * 128,
            3, cvec, As[0], As[1], Bs[0], Bs[1]);
}

// ---------------------------------------------------------------------------
// Flash attention on tf32 mma. CTA: 128 q rows x 64 k cols/tile, 8 warps,
// each warp owns 16 q rows. QK^T: plain tf32. PV: split-P (hi+lo) x centered V.
// Writes g_obd = (ctx-0.5)*(emb1-emb0) directly (centered out-bits).
// ---------------------------------------------------------------------------
#define KT_P 72   // Kt/Vs pitch (72 mod 32 == 8 -> conflict-free frag loads)
#define P_P 68    // P pitch

// swizzled Kt index: spread transpose-store banks while keeping loads clean
__device__ __forceinline__ int kt_idx(int d, int kr) {
  return d * KT_P + (kr ^ (((d >> 2) & 7) << 3));
}

__global__ __launch_bounds__(256)
void attn_mma_kernel(const int* __restrict__ amask,
                     const float* __restrict__ emb0,
                     const float* __restrict__ emb1) {
  extern __shared__ float smn[];
  float* Kt = smn;                       // [64 d][KT_P] swizzled K^T
  float* Vs = Kt + 64 * KT_P;            // [64 kr][KT_P] centered V
  float* Pw = Vs + 64 * KT_P;            // [8 warps][16][P_P]
  int*   Ms = (int*)(Pw + 8 * 16 * P_P);

  const int qt = blockIdx.x;
  const int h  = blockIdx.y;
  const int b  = blockIdx.z;
  const int kv = h >> 2;
  const int tid = threadIdx.x;
  const int w = tid >> 5;
  const int lane = tid & 31;
  const int lg = lane >> 2;
  const int lt = lane & 3;
  const int q0 = qt * 128;
  const int r0 = q0 + w * 16 + lg;
  const int r1 = r0 + 8;

  // Q fragments (tf32), loaded once
  uint32_t aq[8][4];
  {
    const float* Q0 = g_qb + (((size_t)b * S_N + r0) * H_N + h) * QKB_N;
    const float* Q1 = g_qb + (((size_t)b * S_N + r1) * H_N + h) * QKB_N;
#pragma unroll
    for (int ks = 0; ks < 8; ++ks) {
      aq[ks][0] = f2tf32(Q0[ks * 8 + lt]);
      aq[ks][1] = f2tf32(Q1[ks * 8 + lt]);
      aq[ks][2] = f2tf32(Q0[ks * 8 + lt + 4]);
      aq[ks][3] = f2tf32(Q1[ks * 8 + lt + 4]);
    }
  }

  float acc[8][4];
#pragma unroll
  for (int nj = 0; nj < 8; ++nj) {
#pragma unroll
    for (int t = 0; t < 4; ++t) { acc[nj][t] = 0.f; }
  }
  float m0 = -3.402823466e38f, m1 = -3.402823466e38f;
  float l0 = 0.f, l1 = 0.f;

  float* Pme = Pw + w * 16 * P_P;

  const int nkt = 2 * qt + 2;
  for (int kt = 0; kt < nkt; ++kt) {
    const int k0 = kt * 64;
    __syncthreads();
#pragma unroll
    for (int it = 0; it < 4; ++it) {
      int c = tid + it * 256;
      int krow = c >> 4;
      int d0 = (c & 15) * 4;
      size_t base = ((size_t)b * S_N + k0 + krow) * KV_N + kv;
      float4 kk = *(const float4*)&g_kb[base * QKB_N + d0];
      Kt[kt_idx(d0 + 0, krow)] = kk.x;
      Kt[kt_idx(d0 + 1, krow)] = kk.y;
      Kt[kt_idx(d0 + 2, krow)] = kk.z;
      Kt[kt_idx(d0 + 3, krow)] = kk.w;
      float4 vv = *(const float4*)&g_vp[base * VB_N + d0];
      vv.x -= 0.5f; vv.y -= 0.5f; vv.z -= 0.5f; vv.w -= 0.5f;
      *(float4*)&Vs[krow * KT_P + d0] = vv;
    }
    if (tid < 64) { Ms[tid] = amask[b * S_N + k0 + tid]; }
    __syncthreads();

    // ---- S = Q @ K^T ----
    float s[8][4];
#pragma unroll
    for (int nj = 0; nj < 8; ++nj) {
#pragma unroll
      for (int t = 0; t < 4; ++t) { s[nj][t] = 0.f; }
    }
#pragma unroll
    for (int ks = 0; ks < 8; ++ks) {
      const int dlo = ks * 8 + lt;
      const int dhi = dlo + 4;
#pragma unroll
      for (int nj = 0; nj < 8; ++nj) {
        uint32_t bb[2];
        bb[0] = f2tf32(Kt[kt_idx(dlo, nj * 8 + lg)]);
        bb[1] = f2tf32(Kt[kt_idx(dhi, nj * 8 + lg)]);
        mma_tf32(s[nj], aq[ks], bb);
      }
    }

    // ---- scale + mask ----
#pragma unroll
    for (int nj = 0; nj < 8; ++nj) {
      int c0i = nj * 8 + lt * 2;
      int kc0 = k0 + c0i;
      int kc1 = kc0 + 1;
      bool mk0 = Ms[c0i] != 0;
      bool mk1 = Ms[c0i + 1] != 0;
      s[nj][0] = (kc0 <= r0 && mk0) ? s[nj][0] * (1.f / 64.f) : -3.402823466e38f;
      s[nj][1] = (kc1 <= r0 && mk1) ? s[nj][1] * (1.f / 64.f) : -3.402823466e38f;
      s[nj][2] = (kc0 <= r1 && mk0) ? s[nj][2] * (1.f / 64.f) : -3.402823466e38f;
      s[nj][3] = (kc1 <= r1 && mk1) ? s[nj][3] * (1.f / 64.f) : -3.402823466e38f;
    }

    // ---- online softmax (row spread over 4 lanes: xor 1,2) ----
    float rm0 = -3.402823466e38f, rm1 = -3.402823466e38f;
#pragma unroll
    for (int nj = 0; nj < 8; ++nj) {
      rm0 = fmaxf(rm0, fmaxf(s[nj][0], s[nj][1]));
      rm1 = fmaxf(rm1, fmaxf(s[nj][2], s[nj][3]));
    }
    rm0 = fmaxf(rm0, __shfl_xor_sync(0xffffffffu, rm0, 1));
    rm0 = fmaxf(rm0, __shfl_xor_sync(0xffffffffu, rm0, 2));
    rm1 = fmaxf(rm1, __shfl_xor_sync(0xffffffffu, rm1, 1));
    rm1 = fmaxf(rm1, __shfl_xor_sync(0xffffffffu, rm1, 2));
    float mn0 = fmaxf(m0, rm0);
    float mn1 = fmaxf(m1, rm1);
    float sc0 = __expf(m0 - mn0);
    float sc1 = __expf(m1 - mn1);
    m0 = mn0; m1 = mn1;
    float rs0 = 0.f, rs1 = 0.f;
#pragma unroll
    for (int nj = 0; nj < 8; ++nj) {
      float p00 = __expf(s[nj][0] - m0);
      float p01 = __expf(s[nj][1] - m0);
      float p10 = __expf(s[nj][2] - m1);
      float p11 = __expf(s[nj][3] - m1);
      rs0 += p00 + p01;
      rs1 += p10 + p11;
      float2 q2a = make_float2(p00, p01);
      float2 q2b = make_float2(p10, p11);
      *(float2*)&Pme[lg * P_P + nj * 8 + lt * 2] = q2a;
      *(float2*)&Pme[(lg + 8) * P_P + nj * 8 + lt * 2] = q2b;
      acc[nj][0] *= sc0; acc[nj][1] *= sc0;
      acc[nj][2] *= sc1; acc[nj][3] *= sc1;
    }
    rs0 += __shfl_xor_sync(0xffffffffu, rs0, 1);
    rs0 += __shfl_xor_sync(0xffffffffu, rs0, 2);
    rs1 += __shfl_xor_sync(0xffffffffu, rs1, 1);
    rs1 += __shfl_xor_sync(0xffffffffu, rs1, 2);
    l0 = l0 * sc0 + rs0;
    l1 = l1 * sc1 + rs1;
    __syncwarp();

    // ---- O += P @ V'  (split-P tf32x2) ----
#pragma unroll
    for (int ks = 0; ks < 8; ++ks) {
      float p0 = Pme[lg * P_P + ks * 8 + lt];
      float p1 = Pme[(lg + 8) * P_P + ks * 8 + lt];
      float p2 = Pme[lg * P_P + ks * 8 + lt + 4];
      float p3 = Pme[(lg + 8) * P_P + ks * 8 + lt + 4];
      uint32_t hi[4], lo[4];
      hi[0] = f2tf32(p0); lo[0] = f2tf32(p0 - __uint_as_float(hi[0]));
      hi[1] = f2tf32(p1); lo[1] = f2tf32(p1 - __uint_as_float(hi[1]));
      hi[2] = f2tf32(p2); lo[2] = f2tf32(p2 - __uint_as_float(hi[2]));
      hi[3] = f2tf32(p3); lo[3] = f2tf32(p3 - __uint_as_float(hi[3]));
      const int vlo = (ks * 8 + lt) * KT_P;
      const int vhi = vlo + 4 * KT_P;
#pragma unroll
      for (int nj = 0; nj < 8; ++nj) {
        uint32_t bb[2];
        bb[0] = f2tf32(Vs[vlo + nj * 8 + lg]);
        bb[1] = f2tf32(Vs[vhi + nj * 8 + lg]);
        mma_tf32(acc[nj], hi, bb);
        mma_tf32(acc[nj], lo, bb);
      }
    }
  }

  // ---- epilogue: centered out-bits ----
  float inv0 = 1.f / l0;
  float inv1 = 1.f / l1;
#pragma unroll
  for (int nj = 0; nj < 8; ++nj) {
    int vc = nj * 8 + lt * 2;
    float d0 = emb1[h * VB_N + vc] - emb0[h * VB_N + vc];
    float d1 = emb1[h * VB_N + vc + 1] - emb0[h * VB_N + vc + 1];
    float2 o0 = make_float2(acc[nj][0] * inv0 * d0, acc[nj][1] * inv0 * d1);
    float2 o1 = make_float2(acc[nj][2] * inv1 * d0, acc[nj][3] * inv1 * d1);
    *(float2*)&g_obd[(((size_t)b * S_N + r0) * H_N + h) * VB_N + vc] = o0;
    *(float2*)&g_obd[(((size_t)b * S_N + r1) * H_N + h) * VB_N + vc] = o1;
  }
}

// ---------------------------------------------------------------------------
extern "C" void kernel_launch(void* const* d_in, const int* in_sizes, int n_in,
                              void* d_out, int out_size) {
  const float* x  = (const float*)d_in[0];
  const int*   am = (const int*)d_in[1];
  const float* Wq = (const float*)d_in[2];
  const float* Wk = (const float*)d_in[3];
  const float* Wv = (const float*)d_in[4];
  const float* Wo = (const float*)d_in[5];
  const float* e0 = (const float*)d_in[6];
  const float* e1 = (const float*)d_in[7];
  float* out = (float*)d_out;

  float* qb;  float* kb;  float* vp;  float* obd;  float* cvec;
  cudaGetSymbolAddress((void**)&qb, g_qb);
  cudaGetSymbolAddress((void**)&kb, g_kb);
  cudaGetSymbolAddress((void**)&vp, g_vp);
  cudaGetSymbolAddress((void**)&obd, g_obd);
  cudaGetSymbolAddress((void**)&cvec, g_cvec);

  const int M = MTOT;

  cvec_kernel<<<HID_N / 256, 256>>>(e0, e1, Wo);

  // fused Q/K/V projections
  gemm_qkv<<<dim3(12, M / 128), 256>>>(x, Wq, Wk, Wv, qb, kb, vp);

  // flash attention (tf32 mma) + centered out-bits epilogue
  size_t asmem = (size_t)(64 * KT_P + 64 * KT_P + 8 * 16 * P_P) * sizeof(float)
               + 64 * sizeof(int);
  cudaFuncSetAttribute(attn_mma_kernel, cudaFuncAttributeMaxDynamicSharedMemorySize, (int)asmem);
  attn_mma_kernel<<<dim3(S_N / 128, H_N, B_N), 256, asmem>>>(am, e0, e1);

  // output projection + const-vector epilogue
  gemm_out<<<dim3(HID_N / 128, M / 128), 256>>>(obd, Wo, out, cvec);
}

// round 6
// speedup vs baseline: 3.1719x; 1.0214x over previous
#include <cuda_runtime.h>
#include <stdint.h>
#include <math.h>

#define B_N 2
#define S_N 2048
#define HID_N 2048
#define H_N 16
#define KV_N 4
#define QKB_N 64
#define VB_N 64
#define MTOT (B_N * S_N)

// ---- scratch (__device__ globals: allocation-free rule) ----
__device__ float g_qb[(size_t)MTOT * H_N * QKB_N];    // round(tanh(x@Wq))
__device__ float g_kb[(size_t)MTOT * KV_N * QKB_N];   // round(tanh(x@Wk))
__device__ float g_vp[(size_t)MTOT * KV_N * VB_N];    // round(sigm(x@Wv)-0.5)
__device__ float g_obd[(size_t)MTOT * H_N * VB_N];    // round((ctx-.5)*(e1-e0))
__device__ float g_cvec[HID_N];
__device__ float g_xr [(size_t)MTOT * HID_N];         // round(x)
__device__ float g_wqr[(size_t)HID_N * H_N * QKB_N];
__device__ float g_wkr[(size_t)HID_N * KV_N * QKB_N];
__device__ float g_wvr[(size_t)HID_N * KV_N * VB_N];
__device__ float g_wor[(size_t)H_N * VB_N * HID_N];

// ---- helpers ----
__device__ __forceinline__ uint32_t smem_u32(const void* p) {
  return (uint32_t)__cvta_generic_to_shared(p);
}

__device__ __forceinline__ void cp16(uint32_t dst, const void* src) {
  asm volatile("cp.async.cg.shared.global [%0], [%1], 16;"
               : : "r"(dst), "l"(src) : "memory");
}

__device__ __forceinline__ void cp_commit() {
  asm volatile("cp.async.commit_group;" : : : "memory");
}

__device__ __forceinline__ void cp_wait0() {
  asm volatile("cp.async.wait_group 0;" : : : "memory");
}

__device__ __forceinline__ uint32_t f2tf32(float v) {
  uint32_t r;
  asm("cvt.rna.tf32.f32 %0, %1;" : "=r"(r) : "f"(v));
  return r;
}

__device__ __forceinline__ float rnd_tf32(float v) {
  return __uint_as_float(f2tf32(v));
}

__device__ __forceinline__ void mma_tf32(float* d, const uint32_t* a, const uint32_t* b) {
  asm volatile(
    "mma.sync.aligned.m16n8k8.row.col.f32.tf32.tf32.f32 "
    "{%0,%1,%2,%3}, {%4,%5,%6,%7}, {%8,%9}, {%0,%1,%2,%3};"
    : "+f"(d[0]), "+f"(d[1]), "+f"(d[2]), "+f"(d[3])
    : "r"(a[0]), "r"(a[1]), "r"(a[2]), "r"(a[3]), "r"(b[0]), "r"(b[1]));
}

// ---- pre-round an fp32 array to tf32 bit patterns ----
__global__ void round_tf32_kernel(const float* __restrict__ in,
                                  float* __restrict__ out, int n4) {
  int i = blockIdx.x * blockDim.x + threadIdx.x;
  if (i < n4) {
    float4 v = ((const float4*)in)[i];
    v.x = rnd_tf32(v.x);
    v.y = rnd_tf32(v.y);
    v.z = rnd_tf32(v.z);
    v.w = rnd_tf32(v.w);
    ((float4*)out)[i] = v;
  }
}

// ---- cvec[n] = sum_k 0.5*(e0[k]+e1[k]) * Wo[k][n] (exact fp32) ----
__global__ void cvec_kernel(const float* __restrict__ e0, const float* __restrict__ e1,
                            const float* __restrict__ Wo) {
  int n = blockIdx.x * blockDim.x + threadIdx.x;
  if (n < HID_N) {
    float s = 0.f;
    for (int k = 0; k < H_N * VB_N; ++k) {
      s = fmaf(0.5f * (e0[k] + e1[k]), Wo[(size_t)k * HID_N + n], s);
    }
    g_cvec[n] = s;
  }
}

// ---------------------------------------------------------------------------
// TF32 tensor-core GEMM body (operands ALREADY tf32-rounded in memory).
// 128x128x16 tile, 256 threads, mma.m16n8k8. No in-loop cvt.
// epi: 1=tanh+round, 2=sigmoid-0.5+round, 3=add cvec[col].
// ---------------------------------------------------------------------------
#define LDA 20
#define LDB 136

__device__ __forceinline__ void gemm_prefetch(
    const float* __restrict__ A, const float* __restrict__ Bm,
    float* AsBuf, float* BsBuf, int tid, int m0, int n0, int kt, int K, int N) {
  {
    int c0 = tid;
    int row = c0 >> 2, kc = (c0 & 3) * 4;
    cp16(smem_u32(AsBuf + row * LDA + kc), A + (size_t)(m0 + row) * K + kt * 16 + kc);
    int c1 = tid + 256;
    int row1 = c1 >> 2, kc1 = (c1 & 3) * 4;
    cp16(smem_u32(AsBuf + row1 * LDA + kc1), A + (size_t)(m0 + row1) * K + kt * 16 + kc1);
  }
  {
    int c0 = tid;
    int row = c0 >> 5, nc = (c0 & 31) * 4;
    cp16(smem_u32(BsBuf + row * LDB + nc), Bm + (size_t)(kt * 16 + row) * N + n0 + nc);
    int c1 = tid + 256;
    int row1 = c1 >> 5, nc1 = (c1 & 31) * 4;
    cp16(smem_u32(BsBuf + row1 * LDB + nc1), Bm + (size_t)(kt * 16 + row1) * N + n0 + nc1);
  }
}

__device__ __forceinline__ void gemm_body(
    const float* __restrict__ A, const float* __restrict__ Bm,
    float* __restrict__ C, int N, int K, int m0, int n0, int epi,
    const float* __restrict__ cvec,
    float* As0, float* As1, float* Bs0, float* Bs1) {
  const int tid = threadIdx.x;
  const int wid = tid >> 5;
  const int lane = tid & 31;
  const int wm = wid & 3;
  const int wn = wid >> 2;
  const int lg = lane >> 2;
  const int lt = lane & 3;

  float acc[2][8][4];
#pragma unroll
  for (int i = 0; i < 2; ++i) {
#pragma unroll
    for (int j = 0; j < 8; ++j) {
#pragma unroll
      for (int t = 0; t < 4; ++t) { acc[i][j][t] = 0.f; }
    }
  }

  const int KT = K / 16;
  gemm_prefetch(A, Bm, As0, Bs0, tid, m0, n0, 0, K, N);
  cp_commit();

  for (int kt = 0; kt < KT; ++kt) {
    float* Asb = (kt & 1) ? As1 : As0;
    float* Bsb = (kt & 1) ? Bs1 : Bs0;
    cp_wait0();
    __syncthreads();
    if (kt + 1 < KT) {
      float* Asn = (kt & 1) ? As0 : As1;
      float* Bsn = (kt & 1) ? Bs0 : Bs1;
      gemm_prefetch(A, Bm, Asn, Bsn, tid, m0, n0, kt + 1, K, N);
      cp_commit();
    }

#pragma unroll
    for (int ks = 0; ks < 2; ++ks) {
      uint32_t a[2][4];
      uint32_t b[8][2];
#pragma unroll
      for (int mi = 0; mi < 2; ++mi) {
        const float* ab = &Asb[(wm * 32 + mi * 16 + lg) * LDA + ks * 8 + lt];
        a[mi][0] = __float_as_uint(ab[0]);
        a[mi][1] = __float_as_uint(ab[8 * LDA]);
        a[mi][2] = __float_as_uint(ab[4]);
        a[mi][3] = __float_as_uint(ab[8 * LDA + 4]);
      }
#pragma unroll
      for (int nj = 0; nj < 8; ++nj) {
        const float* bb = &Bsb[(ks * 8 + lt) * LDB + wn * 64 + nj * 8 + lg];
        b[nj][0] = __float_as_uint(bb[0]);
        b[nj][1] = __float_as_uint(bb[4 * LDB]);
      }
#pragma unroll
      for (int mi = 0; mi < 2; ++mi) {
#pragma unroll
        for (int nj = 0; nj < 8; ++nj) { mma_tf32(acc[mi][nj], a[mi], b[nj]); }
      }
    }
    __syncthreads();
  }

#pragma unroll
  for (int mi = 0; mi < 2; ++mi) {
    int r0 = m0 + wm * 32 + mi * 16 + lg;
#pragma unroll
    for (int nj = 0; nj < 8; ++nj) {
      int col = n0 + wn * 64 + nj * 8 + lt * 2;
#pragma unroll
      for (int half = 0; half < 2; ++half) {
        int row = r0 + half * 8;
        float v0 = acc[mi][nj][half * 2 + 0];
        float v1 = acc[mi][nj][half * 2 + 1];
        if (epi == 1) {
          v0 = rnd_tf32(tanhf(v0));
          v1 = rnd_tf32(tanhf(v1));
        } else if (epi == 2) {
          v0 = rnd_tf32(1.f / (1.f + __expf(-v0)) - 0.5f);
          v1 = rnd_tf32(1.f / (1.f + __expf(-v1)) - 0.5f);
        } else if (epi == 3) {
          v0 += cvec[col]; v1 += cvec[col + 1];
        }
        float2 v2 = make_float2(v0, v1);
        *(float2*)&C[(size_t)row * N + col] = v2;
      }
    }
  }
}

// Fused Q/K/V projection: grid.x = 12 column tiles (0-7 Q, 8-9 K, 10-11 V).
__global__ __launch_bounds__(256, 2)
void gemm_qkv(const float* __restrict__ x,
              const float* __restrict__ Wq, const float* __restrict__ Wk,
              const float* __restrict__ Wv,
              float* __restrict__ qb, float* __restrict__ kb, float* __restrict__ vp) {
  __shared__ float As[2][128 * LDA];
  __shared__ float Bs[2][16 * LDB];
  const int xt = blockIdx.x;
  const int m0 = blockIdx.y * 128;
  const float* Bm;
  float* C;
  int N, n0, epi;
  if (xt < 8) {
    Bm = Wq; C = qb; N = H_N * QKB_N; n0 = xt * 128; epi = 1;
  } else if (xt < 10) {
    Bm = Wk; C = kb; N = KV_N * QKB_N; n0 = (xt - 8) * 128; epi = 1;
  } else {
    Bm = Wv; C = vp; N = KV_N * VB_N; n0 = (xt - 10) * 128; epi = 2;
  }
  gemm_body(x, Bm, C, N, HID_N, m0, n0, epi, (const float*)0,
            As[0], As[1], Bs[0], Bs[1]);
}

// Output projection: out = obd @ Wo + cvec
__global__ __launch_bounds__(256, 2)
void gemm_out(const float* __restrict__ obd, const float* __restrict__ Wo,
              float* __restrict__ out, const float* __restrict__ cvec) {
  __shared__ float As[2][128 * LDA];
  __shared__ float Bs[2][16 * LDB];
  gemm_body(obd, Wo, out, HID_N, H_N * VB_N, blockIdx.y * 128, blockIdx.x * 128,
            3, cvec, As[0], As[1], Bs[0], Bs[1]);
}

// ---------------------------------------------------------------------------
// Flash attention on tf32 mma (all operands pre-rounded; V pre-centered).
// CTA: 128 q rows x 64 k cols/tile, 8 warps x 16 q rows.
// QK^T plain tf32; PV split-P (hi+lo). Writes rounded centered out-bits.
// ---------------------------------------------------------------------------
#define KT_P 72
#define P_P 68

__device__ __forceinline__ int kt_idx(int d, int kr) {
  return d * KT_P + (kr ^ (((d >> 2) & 7) << 3));
}

__global__ __launch_bounds__(256)
void attn_mma_kernel(const int* __restrict__ amask,
                     const float* __restrict__ emb0,
                     const float* __restrict__ emb1) {
  extern __shared__ float smn[];
  float* Kt = smn;                       // [64 d][KT_P] swizzled K^T
  float* Vs = Kt + 64 * KT_P;            // [64 kr][KT_P] centered V
  float* Pw = Vs + 64 * KT_P;            // [8 warps][16][P_P]
  int*   Ms = (int*)(Pw + 8 * 16 * P_P);

  const int qt = blockIdx.x;
  const int h  = blockIdx.y;
  const int b  = blockIdx.z;
  const int kv = h >> 2;
  const int tid = threadIdx.x;
  const int w = tid >> 5;
  const int lane = tid & 31;
  const int lg = lane >> 2;
  const int lt = lane & 3;
  const int q0 = qt * 128;
  const int r0 = q0 + w * 16 + lg;
  const int r1 = r0 + 8;

  // Q fragments (pre-rounded tf32 in memory)
  uint32_t aq[8][4];
  {
    const float* Q0 = g_qb + (((size_t)b * S_N + r0) * H_N + h) * QKB_N;
    const float* Q1 = g_qb + (((size_t)b * S_N + r1) * H_N + h) * QKB_N;
#pragma unroll
    for (int ks = 0; ks < 8; ++ks) {
      aq[ks][0] = __float_as_uint(Q0[ks * 8 + lt]);
      aq[ks][1] = __float_as_uint(Q1[ks * 8 + lt]);
      aq[ks][2] = __float_as_uint(Q0[ks * 8 + lt + 4]);
      aq[ks][3] = __float_as_uint(Q1[ks * 8 + lt + 4]);
    }
  }

  float acc[8][4];
#pragma unroll
  for (int nj = 0; nj < 8; ++nj) {
#pragma unroll
    for (int t = 0; t < 4; ++t) { acc[nj][t] = 0.f; }
  }
  float m0 = -3.402823466e38f, m1 = -3.402823466e38f;
  float l0 = 0.f, l1 = 0.f;

  float* Pme = Pw + w * 16 * P_P;

  const int nkt = 2 * qt + 2;
  for (int kt = 0; kt < nkt; ++kt) {
    const int k0 = kt * 64;
    __syncthreads();
#pragma unroll
    for (int it = 0; it < 4; ++it) {
      int c = tid + it * 256;
      int krow = c >> 4;
      int d0 = (c & 15) * 4;
      size_t base = ((size_t)b * S_N + k0 + krow) * KV_N + kv;
      float4 kk = *(const float4*)&g_kb[base * QKB_N + d0];
      Kt[kt_idx(d0 + 0, krow)] = kk.x;
      Kt[kt_idx(d0 + 1, krow)] = kk.y;
      Kt[kt_idx(d0 + 2, krow)] = kk.z;
      Kt[kt_idx(d0 + 3, krow)] = kk.w;
      float4 vv = *(const float4*)&g_vp[base * VB_N + d0];
      *(float4*)&Vs[krow * KT_P + d0] = vv;
    }
    if (tid < 64) { Ms[tid] = amask[b * S_N + k0 + tid]; }
    __syncthreads();

    // ---- S = Q @ K^T ----
    float s[8][4];
#pragma unroll
    for (int nj = 0; nj < 8; ++nj) {
#pragma unroll
      for (int t = 0; t < 4; ++t) { s[nj][t] = 0.f; }
    }
#pragma unroll
    for (int ks = 0; ks < 8; ++ks) {
      const int dlo = ks * 8 + lt;
      const int dhi = dlo + 4;
#pragma unroll
      for (int nj = 0; nj < 8; ++nj) {
        uint32_t bb[2];
        bb[0] = __float_as_uint(Kt[kt_idx(dlo, nj * 8 + lg)]);
        bb[1] = __float_as_uint(Kt[kt_idx(dhi, nj * 8 + lg)]);
        mma_tf32(s[nj], aq[ks], bb);
      }
    }

    // ---- scale + mask ----
#pragma unroll
    for (int nj = 0; nj < 8; ++nj) {
      int c0i = nj * 8 + lt * 2;
      int kc0 = k0 + c0i;
      int kc1 = kc0 + 1;
      bool mk0 = Ms[c0i] != 0;
      bool mk1 = Ms[c0i + 1] != 0;
      s[nj][0] = (kc0 <= r0 && mk0) ? s[nj][0] * (1.f / 64.f) : -3.402823466e38f;
      s[nj][1] = (kc1 <= r0 && mk1) ? s[nj][1] * (1.f / 64.f) : -3.402823466e38f;
      s[nj][2] = (kc0 <= r1 && mk0) ? s[nj][2] * (1.f / 64.f) : -3.402823466e38f;
      s[nj][3] = (kc1 <= r1 && mk1) ? s[nj][3] * (1.f / 64.f) : -3.402823466e38f;
    }

    // ---- online softmax ----
    float rm0 = -3.402823466e38f, rm1 = -3.402823466e38f;
#pragma unroll
    for (int nj = 0; nj < 8; ++nj) {
      rm0 = fmaxf(rm0, fmaxf(s[nj][0], s[nj][1]));
      rm1 = fmaxf(rm1, fmaxf(s[nj][2], s[nj][3]));
    }
    rm0 = fmaxf(rm0, __shfl_xor_sync(0xffffffffu, rm0, 1));
    rm0 = fmaxf(rm0, __shfl_xor_sync(0xffffffffu, rm0, 2));
    rm1 = fmaxf(rm1, __shfl_xor_sync(0xffffffffu, rm1, 1));
    rm1 = fmaxf(rm1, __shfl_xor_sync(0xffffffffu, rm1, 2));
    float mn0 = fmaxf(m0, rm0);
    float mn1 = fmaxf(m1, rm1);
    float sc0 = __expf(m0 - mn0);
    float sc1 = __expf(m1 - mn1);
    m0 = mn0; m1 = mn1;
    float rs0 = 0.f, rs1 = 0.f;
#pragma unroll
    for (int nj = 0; nj < 8; ++nj) {
      float p00 = __expf(s[nj][0] - m0);
      float p01 = __expf(s[nj][1] - m0);
      float p10 = __expf(s[nj][2] - m1);
      float p11 = __expf(s[nj][3] - m1);
      rs0 += p00 + p01;
      rs1 += p10 + p11;
      float2 q2a = make_float2(p00, p01);
      float2 q2b = make_float2(p10, p11);
      *(float2*)&Pme[lg * P_P + nj * 8 + lt * 2] = q2a;
      *(float2*)&Pme[(lg + 8) * P_P + nj * 8 + lt * 2] = q2b;
      acc[nj][0] *= sc0; acc[nj][1] *= sc0;
      acc[nj][2] *= sc1; acc[nj][3] *= sc1;
    }
    rs0 += __shfl_xor_sync(0xffffffffu, rs0, 1);
    rs0 += __shfl_xor_sync(0xffffffffu, rs0, 2);
    rs1 += __shfl_xor_sync(0xffffffffu, rs1, 1);
    rs1 += __shfl_xor_sync(0xffffffffu, rs1, 2);
    l0 = l0 * sc0 + rs0;
    l1 = l1 * sc1 + rs1;
    __syncwarp();

    // ---- O += P @ V'  (split-P tf32x2) ----
#pragma unroll
    for (int ks = 0; ks < 8; ++ks) {
      float p0 = Pme[lg * P_P + ks * 8 + lt];
      float p1 = Pme[(lg + 8) * P_P + ks * 8 + lt];
      float p2 = Pme[lg * P_P + ks * 8 + lt + 4];
      float p3 = Pme[(lg + 8) * P_P + ks * 8 + lt + 4];
      uint32_t hi[4], lo[4];
      hi[0] = f2tf32(p0); lo[0] = f2tf32(p0 - __uint_as_float(hi[0]));
      hi[1] = f2tf32(p1); lo[1] = f2tf32(p1 - __uint_as_float(hi[1]));
      hi[2] = f2tf32(p2); lo[2] = f2tf32(p2 - __uint_as_float(hi[2]));
      hi[3] = f2tf32(p3); lo[3] = f2tf32(p3 - __uint_as_float(hi[3]));
      const int vlo = (ks * 8 + lt) * KT_P;
      const int vhi = vlo + 4 * KT_P;
#pragma unroll
      for (int nj = 0; nj < 8; ++nj) {
        uint32_t bb[2];
        bb[0] = __float_as_uint(Vs[vlo + nj * 8 + lg]);
        bb[1] = __float_as_uint(Vs[vhi + nj * 8 + lg]);
        mma_tf32(acc[nj], hi, bb);
        mma_tf32(acc[nj], lo, bb);
      }
    }
  }

  // ---- epilogue: centered out-bits (rounded to tf32 for the next GEMM) ----
  float inv0 = 1.f / l0;
  float inv1 = 1.f / l1;
#pragma unroll
  for (int nj = 0; nj < 8; ++nj) {
    int vc = nj * 8 + lt * 2;
    float d0 = emb1[h * VB_N + vc] - emb0[h * VB_N + vc];
    float d1 = emb1[h * VB_N + vc + 1] - emb0[h * VB_N + vc + 1];
    float2 o0 = make_float2(rnd_tf32(acc[nj][0] * inv0 * d0),
                            rnd_tf32(acc[nj][1] * inv0 * d1));
    float2 o1 = make_float2(rnd_tf32(acc[nj][2] * inv1 * d0),
                            rnd_tf32(acc[nj][3] * inv1 * d1));
    *(float2*)&g_obd[(((size_t)b * S_N + r0) * H_N + h) * VB_N + vc] = o0;
    *(float2*)&g_obd[(((size_t)b * S_N + r1) * H_N + h) * VB_N + vc] = o1;
  }
}

// ---------------------------------------------------------------------------
extern "C" void kernel_launch(void* const* d_in, const int* in_sizes, int n_in,
                              void* d_out, int out_size) {
  const float* x  = (const float*)d_in[0];
  const int*   am = (const int*)d_in[1];
  const float* Wq = (const float*)d_in[2];
  const float* Wk = (const float*)d_in[3];
  const float* Wv = (const float*)d_in[4];
  const float* Wo = (const float*)d_in[5];
  const float* e0 = (const float*)d_in[6];
  const float* e1 = (const float*)d_in[7];
  float* out = (float*)d_out;

  float* qb;  float* kb;  float* vp;  float* obd;  float* cvec;
  float* xr;  float* wqr; float* wkr; float* wvr;  float* wor;
  cudaGetSymbolAddress((void**)&qb, g_qb);
  cudaGetSymbolAddress((void**)&kb, g_kb);
  cudaGetSymbolAddress((void**)&vp, g_vp);
  cudaGetSymbolAddress((void**)&obd, g_obd);
  cudaGetSymbolAddress((void**)&cvec, g_cvec);
  cudaGetSymbolAddress((void**)&xr, g_xr);
  cudaGetSymbolAddress((void**)&wqr, g_wqr);
  cudaGetSymbolAddress((void**)&wkr, g_wkr);
  cudaGetSymbolAddress((void**)&wvr, g_wvr);
  cudaGetSymbolAddress((void**)&wor, g_wor);

  const int M = MTOT;

  // pre-round all GEMM operands to tf32 (idempotent => numerics unchanged)
  round_tf32_kernel<<<(M * HID_N / 4 + 255) / 256, 256>>>(x, xr, M * HID_N / 4);
  round_tf32_kernel<<<(HID_N * H_N * QKB_N / 4 + 255) / 256, 256>>>(Wq, wqr, HID_N * H_N * QKB_N / 4);
  round_tf32_kernel<<<(HID_N * KV_N * QKB_N / 4 + 255) / 256, 256>>>(Wk, wkr, HID_N * KV_N * QKB_N / 4);
  round_tf32_kernel<<<(HID_N * KV_N * VB_N / 4 + 255) / 256, 256>>>(Wv, wvr, HID_N * KV_N * VB_N / 4);
  round_tf32_kernel<<<(H_N * VB_N * HID_N / 4 + 255) / 256, 256>>>(Wo, wor, H_N * VB_N * HID_N / 4);
  cvec_kernel<<<HID_N / 256, 256>>>(e0, e1, Wo);

  // fused Q/K/V projections (+ round epilogues)
  gemm_qkv<<<dim3(12, M / 128), 256>>>(xr, wqr, wkr, wvr, qb, kb, vp);

  // flash attention (tf32 mma) + centered rounded out-bits epilogue
  size_t asmem = (size_t)(64 * KT_P + 64 * KT_P + 8 * 16 * P_P) * sizeof(float)
               + 64 * sizeof(int);
  cudaFuncSetAttribute(attn_mma_kernel, cudaFuncAttributeMaxDynamicSharedMemorySize, (int)asmem);
  attn_mma_kernel<<<dim3(S_N / 128, H_N, B_N), 256, asmem>>>(am, e0, e1);

  // output projection + const-vector epilogue
  gemm_out<<<dim3(HID_N / 128, M / 128), 256>>>(obd, wor, out, cvec);
}

// round 7
// speedup vs baseline: 3.5398x; 1.1160x over previous
#include <cuda_runtime.h>
#include <stdint.h>
#include <math.h>

#define B_N 2
#define S_N 2048
#define HID_N 2048
#define H_N 16
#define KV_N 4
#define QKB_N 64
#define VB_N 64
#define MTOT (B_N * S_N)

// ---- scratch (__device__ globals: allocation-free rule) ----
__device__ float g_qb[(size_t)MTOT * H_N * QKB_N];    // round(tanh(x@Wq))
__device__ float g_kb[(size_t)MTOT * KV_N * QKB_N];   // round(tanh(x@Wk))
__device__ float g_vp[(size_t)MTOT * KV_N * VB_N];    // round(sigm(x@Wv)-0.5)
__device__ float g_obd[(size_t)MTOT * H_N * VB_N];    // round((ctx-.5)*(e1-e0))
__device__ float g_cvec[HID_N];
__device__ float g_xr [(size_t)MTOT * HID_N];         // round(x)
__device__ float g_wqt[(size_t)(H_N * QKB_N) * HID_N];   // round(Wq^T) [N][K]
__device__ float g_wkt[(size_t)(KV_N * QKB_N) * HID_N];  // round(Wk^T)
__device__ float g_wvt[(size_t)(KV_N * VB_N) * HID_N];   // round(Wv^T)
__device__ float g_wot[(size_t)HID_N * (H_N * VB_N)];    // round(Wo^T)

// ---- helpers ----
__device__ __forceinline__ uint32_t smem_u32(const void* p) {
  return (uint32_t)__cvta_generic_to_shared(p);
}

__device__ __forceinline__ void cp16(uint32_t dst, const void* src) {
  asm volatile("cp.async.cg.shared.global [%0], [%1], 16;"
               : : "r"(dst), "l"(src) : "memory");
}

__device__ __forceinline__ void cp_commit() {
  asm volatile("cp.async.commit_group;" : : : "memory");
}

__device__ __forceinline__ void cp_wait0() {
  asm volatile("cp.async.wait_group 0;" : : : "memory");
}

__device__ __forceinline__ uint32_t f2tf32(float v) {
  uint32_t r;
  asm("cvt.rna.tf32.f32 %0, %1;" : "=r"(r) : "f"(v));
  return r;
}

__device__ __forceinline__ float rnd_tf32(float v) {
  return __uint_as_float(f2tf32(v));
}

__device__ __forceinline__ void ldsm4(uint32_t* r, uint32_t a) {
  asm volatile("ldmatrix.sync.aligned.m8n8.x4.shared.b16 {%0,%1,%2,%3}, [%4];"
               : "=r"(r[0]), "=r"(r[1]), "=r"(r[2]), "=r"(r[3])
               : "r"(a));
}

__device__ __forceinline__ void mma_tf32(float* d, const uint32_t* a, const uint32_t* b) {
  asm volatile(
    "mma.sync.aligned.m16n8k8.row.col.f32.tf32.tf32.f32 "
    "{%0,%1,%2,%3}, {%4,%5,%6,%7}, {%8,%9}, {%0,%1,%2,%3};"
    : "+f"(d[0]), "+f"(d[1]), "+f"(d[2]), "+f"(d[3])
    : "r"(a[0]), "r"(a[1]), "r"(a[2]), "r"(a[3]), "r"(b[0]), "r"(b[1]));
}

// ---- fp32 -> tf32-rounded fp32 ----
__global__ void round_tf32_kernel(const float* __restrict__ in,
                                  float* __restrict__ out, int n4) {
  int i = blockIdx.x * blockDim.x + threadIdx.x;
  if (i < n4) {
    float4 v = ((const float4*)in)[i];
    v.x = rnd_tf32(v.x);
    v.y = rnd_tf32(v.y);
    v.z = rnd_tf32(v.z);
    v.w = rnd_tf32(v.w);
    ((float4*)out)[i] = v;
  }
}

// ---- transpose + round: out[n][k] = rnd(in[k][n]) ----
__global__ void transpose_round_kernel(const float* __restrict__ in,
                                       float* __restrict__ out, int K, int N) {
  __shared__ float t[32][33];
  const int tx = threadIdx.x & 31;
  const int ty = threadIdx.x >> 5;   // 0..7
  const int n0 = blockIdx.x * 32;
  const int k0 = blockIdx.y * 32;
#pragma unroll
  for (int i = 0; i < 4; ++i) {
    int k = k0 + ty + i * 8;
    t[ty + i * 8][tx] = in[(size_t)k * N + n0 + tx];
  }
  __syncthreads();
#pragma unroll
  for (int i = 0; i < 4; ++i) {
    int n = n0 + ty + i * 8;
    out[(size_t)n * K + k0 + tx] = rnd_tf32(t[tx][ty + i * 8]);
  }
}

// ---- cvec[n] = sum_k 0.5*(e0[k]+e1[k]) * Wo[k][n] (exact fp32) ----
__global__ void cvec_kernel(const float* __restrict__ e0, const float* __restrict__ e1,
                            const float* __restrict__ Wo) {
  int n = blockIdx.x * blockDim.x + threadIdx.x;
  if (n < HID_N) {
    float s = 0.f;
    for (int k = 0; k < H_N * VB_N; ++k) {
      s = fmaf(0.5f * (e0[k] + e1[k]), Wo[(size_t)k * HID_N + n], s);
    }
    g_cvec[n] = s;
  }
}

// ---------------------------------------------------------------------------
// TF32 GEMM: C[M,N] = epi(A[M,K] @ BT[N,K]^T). Operands tf32-pre-rounded.
// 128x128x16 tile, 256 threads, mma.m16n8k8, ldmatrix fragment loads.
// A smem [128 m][16 k] pitch 20; B smem [128 n][16 k] pitch 20.
// epi: 1=tanh+round, 2=sigmoid-0.5+round, 3=add cvec[col].
// ---------------------------------------------------------------------------
#define LDA 20

__device__ __forceinline__ void gemm_prefetch(
    const float* __restrict__ A, const float* __restrict__ BT,
    float* AsBuf, float* BsBuf, int tid, int m0, int n0, int kt, int K) {
  {
    int row = tid >> 2, kc = (tid & 3) * 4;
    cp16(smem_u32(AsBuf + row * LDA + kc), A + (size_t)(m0 + row) * K + kt * 16 + kc);
    cp16(smem_u32(AsBuf + (row + 64) * LDA + kc),
         A + (size_t)(m0 + row + 64) * K + kt * 16 + kc);
    cp16(smem_u32(BsBuf + row * LDA + kc), BT + (size_t)(n0 + row) * K + kt * 16 + kc);
    cp16(smem_u32(BsBuf + (row + 64) * LDA + kc),
         BT + (size_t)(n0 + row + 64) * K + kt * 16 + kc);
  }
}

__device__ __forceinline__ void gemm_body(
    const float* __restrict__ A, const float* __restrict__ BT,
    float* __restrict__ C, int N, int K, int m0, int n0, int epi,
    const float* __restrict__ cvec,
    float* As0, float* As1, float* Bs0, float* Bs1) {
  const int tid = threadIdx.x;
  const int wid = tid >> 5;
  const int lane = tid & 31;
  const int wm = wid & 3;
  const int wn = wid >> 2;
  const int lg = lane >> 2;
  const int lt = lane & 3;
  // ldmatrix per-lane addressing pieces
  const int rA = lane & 15;                 // row within 16-row block
  const int kaddA = ((lane >> 4) << 2);     // k chunk select for A
  const int rB = ((lane >> 4) << 3) + (lane & 7);  // row within 16-row block (B)
  const int kaddB = (((lane >> 3) & 1) << 2);      // k chunk select for B

  float acc[2][8][4];
#pragma unroll
  for (int i = 0; i < 2; ++i) {
#pragma unroll
    for (int j = 0; j < 8; ++j) {
#pragma unroll
      for (int t = 0; t < 4; ++t) { acc[i][j][t] = 0.f; }
    }
  }

  const int KT = K / 16;
  gemm_prefetch(A, BT, As0, Bs0, tid, m0, n0, 0, K);
  cp_commit();

  for (int kt = 0; kt < KT; ++kt) {
    float* Asb = (kt & 1) ? As1 : As0;
    float* Bsb = (kt & 1) ? Bs1 : Bs0;
    cp_wait0();
    __syncthreads();
    if (kt + 1 < KT) {
      float* Asn = (kt & 1) ? As0 : As1;
      float* Bsn = (kt & 1) ? Bs0 : Bs1;
      gemm_prefetch(A, BT, Asn, Bsn, tid, m0, n0, kt + 1, K);
      cp_commit();
    }

#pragma unroll
    for (int ks = 0; ks < 2; ++ks) {
      uint32_t a[2][4];
      uint32_t b[8][2];
#pragma unroll
      for (int mi = 0; mi < 2; ++mi) {
        ldsm4(a[mi], smem_u32(&Asb[(wm * 32 + mi * 16 + rA) * LDA + ks * 8 + kaddA]));
      }
#pragma unroll
      for (int j = 0; j < 4; ++j) {
        uint32_t r[4];
        ldsm4(r, smem_u32(&Bsb[(wn * 64 + j * 16 + rB) * LDA + ks * 8 + kaddB]));
        b[2 * j + 0][0] = r[0];
        b[2 * j + 0][1] = r[1];
        b[2 * j + 1][0] = r[2];
        b[2 * j + 1][1] = r[3];
      }
#pragma unroll
      for (int mi = 0; mi < 2; ++mi) {
#pragma unroll
        for (int nj = 0; nj < 8; ++nj) { mma_tf32(acc[mi][nj], a[mi], b[nj]); }
      }
    }
    __syncthreads();
  }

#pragma unroll
  for (int mi = 0; mi < 2; ++mi) {
    int r0 = m0 + wm * 32 + mi * 16 + lg;
#pragma unroll
    for (int nj = 0; nj < 8; ++nj) {
      int col = n0 + wn * 64 + nj * 8 + lt * 2;
#pragma unroll
      for (int half = 0; half < 2; ++half) {
        int row = r0 + half * 8;
        float v0 = acc[mi][nj][half * 2 + 0];
        float v1 = acc[mi][nj][half * 2 + 1];
        if (epi == 1) {
          v0 = rnd_tf32(tanhf(v0));
          v1 = rnd_tf32(tanhf(v1));
        } else if (epi == 2) {
          v0 = rnd_tf32(1.f / (1.f + __expf(-v0)) - 0.5f);
          v1 = rnd_tf32(1.f / (1.f + __expf(-v1)) - 0.5f);
        } else if (epi == 3) {
          v0 += cvec[col]; v1 += cvec[col + 1];
        }
        float2 v2 = make_float2(v0, v1);
        *(float2*)&C[(size_t)row * N + col] = v2;
      }
    }
  }
}

// Fused Q/K/V projection: grid.x = 12 column tiles (0-7 Q, 8-9 K, 10-11 V).
__global__ __launch_bounds__(256, 2)
void gemm_qkv(const float* __restrict__ x,
              const float* __restrict__ WqT, const float* __restrict__ WkT,
              const float* __restrict__ WvT,
              float* __restrict__ qb, float* __restrict__ kb, float* __restrict__ vp) {
  __shared__ float As[2][128 * LDA];
  __shared__ float Bs[2][128 * LDA];
  const int xt = blockIdx.x;
  const int m0 = blockIdx.y * 128;
  const float* BT;
  float* C;
  int N, n0, epi;
  if (xt < 8) {
    BT = WqT; C = qb; N = H_N * QKB_N; n0 = xt * 128; epi = 1;
  } else if (xt < 10) {
    BT = WkT; C = kb; N = KV_N * QKB_N; n0 = (xt - 8) * 128; epi = 1;
  } else {
    BT = WvT; C = vp; N = KV_N * VB_N; n0 = (xt - 10) * 128; epi = 2;
  }
  gemm_body(x, BT, C, N, HID_N, m0, n0, epi, (const float*)0,
            As[0], As[1], Bs[0], Bs[1]);
}

// Output projection: out = obd @ Wo + cvec
__global__ __launch_bounds__(256, 2)
void gemm_out(const float* __restrict__ obd, const float* __restrict__ WoT,
              float* __restrict__ out, const float* __restrict__ cvec) {
  __shared__ float As[2][128 * LDA];
  __shared__ float Bs[2][128 * LDA];
  gemm_body(obd, WoT, out, HID_N, H_N * VB_N, blockIdx.y * 128, blockIdx.x * 128,
            3, cvec, As[0], As[1], Bs[0], Bs[1]);
}

// ---------------------------------------------------------------------------
// Flash attention on tf32 mma, ldmatrix fragment loads.
// CTA: 128 q rows x 64 k cols/tile, 8 warps x 16 q rows.
// K smem [kr][d] pitch 68, V smem transposed [vcol][kr] pitch 68,
// P smem per-warp [16][68]. Single-pass tf32 PV (no split).
// ---------------------------------------------------------------------------
#define KS_P 68
#define P_P 68

__global__ __launch_bounds__(256)
void attn_mma_kernel(const int* __restrict__ amask,
                     const float* __restrict__ emb0,
                     const float* __restrict__ emb1) {
  extern __shared__ float smn[];
  float* Ks  = smn;                      // [64 kr][KS_P]  K rows (d contiguous)
  float* Vst = Ks + 64 * KS_P;           // [64 vcol][KS_P] V transposed (kr contiguous)
  float* Pw  = Vst + 64 * KS_P;          // [8 warps][16][P_P]
  int*   Ms  = (int*)(Pw + 8 * 16 * P_P);

  const int qt = blockIdx.x;
  const int h  = blockIdx.y;
  const int b  = blockIdx.z;
  const int kv = h >> 2;
  const int tid = threadIdx.x;
  const int w = tid >> 5;
  const int lane = tid & 31;
  const int lg = lane >> 2;
  const int lt = lane & 3;
  const int q0 = qt * 128;
  const int r0 = q0 + w * 16 + lg;
  const int r1 = r0 + 8;
  // ldmatrix addressing pieces
  const int rA = lane & 15;
  const int kaddA = ((lane >> 4) << 2);
  const int rB = ((lane >> 4) << 3) + (lane & 7);
  const int kaddB = (((lane >> 3) & 1) << 2);

  // Q fragments (pre-rounded tf32 in memory)
  uint32_t aq[8][4];
  {
    const float* Q0 = g_qb + (((size_t)b * S_N + r0) * H_N + h) * QKB_N;
    const float* Q1 = g_qb + (((size_t)b * S_N + r1) * H_N + h) * QKB_N;
#pragma unroll
    for (int ks = 0; ks < 8; ++ks) {
      aq[ks][0] = __float_as_uint(Q0[ks * 8 + lt]);
      aq[ks][1] = __float_as_uint(Q1[ks * 8 + lt]);
      aq[ks][2] = __float_as_uint(Q0[ks * 8 + lt + 4]);
      aq[ks][3] = __float_as_uint(Q1[ks * 8 + lt + 4]);
    }
  }

  float acc[8][4];
#pragma unroll
  for (int nj = 0; nj < 8; ++nj) {
#pragma unroll
    for (int t = 0; t < 4; ++t) { acc[nj][t] = 0.f; }
  }
  float m0 = -3.402823466e38f, m1 = -3.402823466e38f;
  float l0 = 0.f, l1 = 0.f;

  float* Pme = Pw + w * 16 * P_P;

  const int nkt = 2 * qt + 2;
  for (int kt = 0; kt < nkt; ++kt) {
    const int k0 = kt * 64;
    __syncthreads();
    // K: direct rows [kr][d]
#pragma unroll
    for (int it = 0; it < 2; ++it) {
      int c = tid + it * 256;
      int krow = c >> 3;
      int d0 = (c & 7) * 8;
      size_t base = (((size_t)b * S_N + k0 + krow) * KV_N + kv) * QKB_N + d0;
      float4 ka = *(const float4*)&g_kb[base];
      float4 kb4 = *(const float4*)&g_kb[base + 4];
      *(float4*)&Ks[krow * KS_P + d0] = ka;
      *(float4*)&Ks[krow * KS_P + d0 + 4] = kb4;
    }
    // V: transposed [vcol][kr]; per thread 4 strided global loads, one float4 store
#pragma unroll
    for (int it = 0; it < 4; ++it) {
      int c = tid + it * 256;
      int vcol = c & 63;
      int kc4 = (c >> 6) << 2;
      float4 vv;
      size_t base = (((size_t)b * S_N + k0 + kc4) * KV_N + kv) * VB_N + vcol;
      vv.x = g_vp[base];
      vv.y = g_vp[base + (size_t)KV_N * VB_N];
      vv.z = g_vp[base + (size_t)2 * KV_N * VB_N];
      vv.w = g_vp[base + (size_t)3 * KV_N * VB_N];
      *(float4*)&Vst[vcol * KS_P + kc4] = vv;
    }
    if (tid < 64) { Ms[tid] = amask[b * S_N + k0 + tid]; }
    __syncthreads();

    // ---- S = Q @ K^T (B-fragments via ldmatrix from Ks) ----
    float s[8][4];
#pragma unroll
    for (int nj = 0; nj < 8; ++nj) {
#pragma unroll
      for (int t = 0; t < 4; ++t) { s[nj][t] = 0.f; }
    }
#pragma unroll
    for (int ks = 0; ks < 8; ++ks) {
#pragma unroll
      for (int j = 0; j < 4; ++j) {
        uint32_t r[4];
        ldsm4(r, smem_u32(&Ks[(j * 16 + rB) * KS_P + ks * 8 + kaddB]));
        mma_tf32(s[2 * j + 0], aq[ks], r + 0);
        mma_tf32(s[2 * j + 1], aq[ks], r + 2);
      }
    }

    // ---- scale + mask ----
#pragma unroll
    for (int nj = 0; nj < 8; ++nj) {
      int c0i = nj * 8 + lt * 2;
      int kc0 = k0 + c0i;
      int kc1 = kc0 + 1;
      bool mk0 = Ms[c0i] != 0;
      bool mk1 = Ms[c0i + 1] != 0;
      s[nj][0] = (kc0 <= r0 && mk0) ? s[nj][0] * (1.f / 64.f) : -3.402823466e38f;
      s[nj][1] = (kc1 <= r0 && mk1) ? s[nj][1] * (1.f / 64.f) : -3.402823466e38f;
      s[nj][2] = (kc0 <= r1 && mk0) ? s[nj][2] * (1.f / 64.f) : -3.402823466e38f;
      s[nj][3] = (kc1 <= r1 && mk1) ? s[nj][3] * (1.f / 64.f) : -3.402823466e38f;
    }

    // ---- online softmax ----
    float rm0 = -3.402823466e38f, rm1 = -3.402823466e38f;
#pragma unroll
    for (int nj = 0; nj < 8; ++nj) {
      rm0 = fmaxf(rm0, fmaxf(s[nj][0], s[nj][1]));
      rm1 = fmaxf(rm1, fmaxf(s[nj][2], s[nj][3]));
    }
    rm0 = fmaxf(rm0, __shfl_xor_sync(0xffffffffu, rm0, 1));
    rm0 = fmaxf(rm0, __shfl_xor_sync(0xffffffffu, rm0, 2));
    rm1 = fmaxf(rm1, __shfl_xor_sync(0xffffffffu, rm1, 1));
    rm1 = fmaxf(rm1, __shfl_xor_sync(0xffffffffu, rm1, 2));
    float mn0 = fmaxf(m0, rm0);
    float mn1 = fmaxf(m1, rm1);
    float sc0 = __expf(m0 - mn0);
    float sc1 = __expf(m1 - mn1);
    m0 = mn0; m1 = mn1;
    float rs0 = 0.f, rs1 = 0.f;
#pragma unroll
    for (int nj = 0; nj < 8; ++nj) {
      float p00 = __expf(s[nj][0] - m0);
      float p01 = __expf(s[nj][1] - m0);
      float p10 = __expf(s[nj][2] - m1);
      float p11 = __expf(s[nj][3] - m1);
      rs0 += p00 + p01;
      rs1 += p10 + p11;
      float2 q2a = make_float2(p00, p01);
      float2 q2b = make_float2(p10, p11);
      *(float2*)&Pme[lg * P_P + nj * 8 + lt * 2] = q2a;
      *(float2*)&Pme[(lg + 8) * P_P + nj * 8 + lt * 2] = q2b;
      acc[nj][0] *= sc0; acc[nj][1] *= sc0;
      acc[nj][2] *= sc1; acc[nj][3] *= sc1;
    }
    rs0 += __shfl_xor_sync(0xffffffffu, rs0, 1);
    rs0 += __shfl_xor_sync(0xffffffffu, rs0, 2);
    rs1 += __shfl_xor_sync(0xffffffffu, rs1, 1);
    rs1 += __shfl_xor_sync(0xffffffffu, rs1, 2);
    l0 = l0 * sc0 + rs0;
    l1 = l1 * sc1 + rs1;
    __syncwarp();

    // ---- O += P @ V' (A=P and B=V via ldmatrix, single tf32 pass) ----
#pragma unroll
    for (int ks = 0; ks < 8; ++ks) {
      uint32_t pr[4];
      ldsm4(pr, smem_u32(&Pme[rA * P_P + ks * 8 + kaddA]));
      uint32_t hi[4];
      hi[0] = f2tf32(__uint_as_float(pr[0]));
      hi[1] = f2tf32(__uint_as_float(pr[1]));
      hi[2] = f2tf32(__uint_as_float(pr[2]));
      hi[3] = f2tf32(__uint_as_float(pr[3]));
#pragma unroll
      for (int j = 0; j < 4; ++j) {
        uint32_t r[4];
        ldsm4(r, smem_u32(&Vst[(j * 16 + rB) * KS_P + ks * 8 + kaddB]));
        mma_tf32(acc[2 * j + 0], hi, r + 0);
        mma_tf32(acc[2 * j + 1], hi, r + 2);
      }
    }
  }

  // ---- epilogue: centered out-bits (rounded to tf32 for the next GEMM) ----
  float inv0 = 1.f / l0;
  float inv1 = 1.f / l1;
#pragma unroll
  for (int nj = 0; nj < 8; ++nj) {
    int vc = nj * 8 + lt * 2;
    float d0 = emb1[h * VB_N + vc] - emb0[h * VB_N + vc];
    float d1 = emb1[h * VB_N + vc + 1] - emb0[h * VB_N + vc + 1];
    float2 o0 = make_float2(rnd_tf32(acc[nj][0] * inv0 * d0),
                            rnd_tf32(acc[nj][1] * inv0 * d1));
    float2 o1 = make_float2(rnd_tf32(acc[nj][2] * inv1 * d0),
                            rnd_tf32(acc[nj][3] * inv1 * d1));
    *(float2*)&g_obd[(((size_t)b * S_N + r0) * H_N + h) * VB_N + vc] = o0;
    *(float2*)&g_obd[(((size_t)b * S_N + r1) * H_N + h) * VB_N + vc] = o1;
  }
}

// ---------------------------------------------------------------------------
extern "C" void kernel_launch(void* const* d_in, const int* in_sizes, int n_in,
                              void* d_out, int out_size) {
  const float* x  = (const float*)d_in[0];
  const int*   am = (const int*)d_in[1];
  const float* Wq = (const float*)d_in[2];
  const float* Wk = (const float*)d_in[3];
  const float* Wv = (const float*)d_in[4];
  const float* Wo = (const float*)d_in[5];
  const float* e0 = (const float*)d_in[6];
  const float* e1 = (const float*)d_in[7];
  float* out = (float*)d_out;

  float* qb;  float* kb;  float* vp;  float* obd;  float* cvec;
  float* xr;  float* wqt; float* wkt; float* wvt;  float* wot;
  cudaGetSymbolAddress((void**)&qb, g_qb);
  cudaGetSymbolAddress((void**)&kb, g_kb);
  cudaGetSymbolAddress((void**)&vp, g_vp);
  cudaGetSymbolAddress((void**)&obd, g_obd);
  cudaGetSymbolAddress((void**)&cvec, g_cvec);
  cudaGetSymbolAddress((void**)&xr, g_xr);
  cudaGetSymbolAddress((void**)&wqt, g_wqt);
  cudaGetSymbolAddress((void**)&wkt, g_wkt);
  cudaGetSymbolAddress((void**)&wvt, g_wvt);
  cudaGetSymbolAddress((void**)&wot, g_wot);

  const int M = MTOT;

  // x: plain round; weights: transpose + round to [N][K]
  round_tf32_kernel<<<(M * HID_N / 4 + 255) / 256, 256>>>(x, xr, M * HID_N / 4);
  transpose_round_kernel<<<dim3((H_N * QKB_N) / 32, HID_N / 32), 256>>>(Wq, wqt, HID_N, H_N * QKB_N);
  transpose_round_kernel<<<dim3((KV_N * QKB_N) / 32, HID_N / 32), 256>>>(Wk, wkt, HID_N, KV_N * QKB_N);
  transpose_round_kernel<<<dim3((KV_N * VB_N) / 32, HID_N / 32), 256>>>(Wv, wvt, HID_N, KV_N * VB_N);
  transpose_round_kernel<<<dim3(HID_N / 32, (H_N * VB_N) / 32), 256>>>(Wo, wot, H_N * VB_N, HID_N);
  cvec_kernel<<<HID_N / 256, 256>>>(e0, e1, Wo);

  // fused Q/K/V projections (+ round epilogues)
  gemm_qkv<<<dim3(12, M / 128), 256>>>(xr, wqt, wkt, wvt, qb, kb, vp);

  // flash attention (tf32 mma + ldmatrix) + centered rounded out-bits epilogue
  size_t asmem = (size_t)(64 * KS_P + 64 * KS_P + 8 * 16 * P_P) * sizeof(float)
               + 64 * sizeof(int);
  cudaFuncSetAttribute(attn_mma_kernel, cudaFuncAttributeMaxDynamicSharedMemorySize, (int)asmem);
  attn_mma_kernel<<<dim3(S_N / 128, H_N, B_N), 256, asmem>>>(am, e0, e1);

  // output projection + const-vector epilogue
  gemm_out<<<dim3(HID_N / 128, M / 128), 256>>>(obd, wot, out, cvec);
}

// round 8
// speedup vs baseline: 3.5440x; 1.0012x over previous
#include <cuda_runtime.h>
#include <stdint.h>
#include <math.h>

#define B_N 2
#define S_N 2048
#define HID_N 2048
#define H_N 16
#define KV_N 4
#define QKB_N 64
#define VB_N 64
#define MTOT (B_N * S_N)

// ---- scratch (__device__ globals: allocation-free rule) ----
__device__ float g_qb[(size_t)MTOT * H_N * QKB_N];    // round(tanh(x@Wq))
__device__ float g_kb[(size_t)MTOT * KV_N * QKB_N];   // round(tanh(x@Wk))
__device__ float g_vp[(size_t)MTOT * KV_N * VB_N];    // round(sigm(x@Wv)-0.5)
__device__ float g_obd[(size_t)MTOT * H_N * VB_N];    // round((ctx-.5)*(e1-e0))
__device__ float g_cvec[HID_N];
__device__ float g_xr [(size_t)MTOT * HID_N];         // round(x)
__device__ float g_wqt[(size_t)(H_N * QKB_N) * HID_N];   // round(Wq^T) [N][K]
__device__ float g_wkt[(size_t)(KV_N * QKB_N) * HID_N];  // round(Wk^T)
__device__ float g_wvt[(size_t)(KV_N * VB_N) * HID_N];   // round(Wv^T)
__device__ float g_wot[(size_t)HID_N * (H_N * VB_N)];    // round(Wo^T)

// ---- helpers ----
__device__ __forceinline__ uint32_t smem_u32(const void* p) {
  return (uint32_t)__cvta_generic_to_shared(p);
}

__device__ __forceinline__ void cp16(uint32_t dst, const void* src) {
  asm volatile("cp.async.cg.shared.global [%0], [%1], 16;"
               : : "r"(dst), "l"(src) : "memory");
}

__device__ __forceinline__ void cp_commit() {
  asm volatile("cp.async.commit_group;" : : : "memory");
}

__device__ __forceinline__ void cp_wait1() {
  asm volatile("cp.async.wait_group 1;" : : : "memory");
}

__device__ __forceinline__ uint32_t f2tf32(float v) {
  uint32_t r;
  asm("cvt.rna.tf32.f32 %0, %1;" : "=r"(r) : "f"(v));
  return r;
}

__device__ __forceinline__ float rnd_tf32(float v) {
  return __uint_as_float(f2tf32(v));
}

__device__ __forceinline__ void ldsm4(uint32_t* r, uint32_t a) {
  asm volatile("ldmatrix.sync.aligned.m8n8.x4.shared.b16 {%0,%1,%2,%3}, [%4];"
               : "=r"(r[0]), "=r"(r[1]), "=r"(r[2]), "=r"(r[3])
               : "r"(a));
}

__device__ __forceinline__ void mma_tf32(float* d, const uint32_t* a, const uint32_t* b) {
  asm volatile(
    "mma.sync.aligned.m16n8k8.row.col.f32.tf32.tf32.f32 "
    "{%0,%1,%2,%3}, {%4,%5,%6,%7}, {%8,%9}, {%0,%1,%2,%3};"
    : "+f"(d[0]), "+f"(d[1]), "+f"(d[2]), "+f"(d[3])
    : "r"(a[0]), "r"(a[1]), "r"(a[2]), "r"(a[3]), "r"(b[0]), "r"(b[1]));
}

// ---- fp32 -> tf32-rounded fp32 ----
__global__ void round_tf32_kernel(const float* __restrict__ in,
                                  float* __restrict__ out, int n4) {
  int i = blockIdx.x * blockDim.x + threadIdx.x;
  if (i < n4) {
    float4 v = ((const float4*)in)[i];
    v.x = rnd_tf32(v.x);
    v.y = rnd_tf32(v.y);
    v.z = rnd_tf32(v.z);
    v.w = rnd_tf32(v.w);
    ((float4*)out)[i] = v;
  }
}

// ---- transpose + round: out[n][k] = rnd(in[k][n]) ----
__global__ void transpose_round_kernel(const float* __restrict__ in,
                                       float* __restrict__ out, int K, int N) {
  __shared__ float t[32][33];
  const int tx = threadIdx.x & 31;
  const int ty = threadIdx.x >> 5;
  const int n0 = blockIdx.x * 32;
  const int k0 = blockIdx.y * 32;
#pragma unroll
  for (int i = 0; i < 4; ++i) {
    int k = k0 + ty + i * 8;
    t[ty + i * 8][tx] = in[(size_t)k * N + n0 + tx];
  }
  __syncthreads();
#pragma unroll
  for (int i = 0; i < 4; ++i) {
    int n = n0 + ty + i * 8;
    out[(size_t)n * K + k0 + tx] = rnd_tf32(t[tx][ty + i * 8]);
  }
}

// ---- cvec[n] = sum_k 0.5*(e0[k]+e1[k]) * Wo[k][n] (exact fp32) ----
__global__ void cvec_kernel(const float* __restrict__ e0, const float* __restrict__ e1,
                            const float* __restrict__ Wo) {
  int n = blockIdx.x * blockDim.x + threadIdx.x;
  if (n < HID_N) {
    float s = 0.f;
    for (int k = 0; k < H_N * VB_N; ++k) {
      s = fmaf(0.5f * (e0[k] + e1[k]), Wo[(size_t)k * HID_N + n], s);
    }
    g_cvec[n] = s;
  }
}

// ---------------------------------------------------------------------------
// TF32 GEMM: C[M,N] = epi(A[M,K] @ BT[N,K]^T). Operands tf32-pre-rounded.
// 128x128x16 tile, 256 threads, mma.m16n8k8, ldmatrix, 3-stage cp.async ring.
// Dynamic smem: 3 stages x (A 2560 + B 2560) floats = 61440 bytes.
// epi: 1=tanh+round, 2=sigmoid-0.5+round, 3=add cvec[col].
// ---------------------------------------------------------------------------
#define LDA 20
#define STAGE_F (128 * LDA * 2)   // floats per stage (A then B)

__device__ __forceinline__ void gemm_prefetch(
    const float* __restrict__ A, const float* __restrict__ BT,
    float* stage, int tid, int m0, int n0, int kt, int K) {
  float* AsBuf = stage;
  float* BsBuf = stage + 128 * LDA;
  int row = tid >> 2, kc = (tid & 3) * 4;
  cp16(smem_u32(AsBuf + row * LDA + kc), A + (size_t)(m0 + row) * K + kt * 16 + kc);
  cp16(smem_u32(AsBuf + (row + 64) * LDA + kc),
       A + (size_t)(m0 + row + 64) * K + kt * 16 + kc);
  cp16(smem_u32(BsBuf + row * LDA + kc), BT + (size_t)(n0 + row) * K + kt * 16 + kc);
  cp16(smem_u32(BsBuf + (row + 64) * LDA + kc),
       BT + (size_t)(n0 + row + 64) * K + kt * 16 + kc);
}

__device__ __forceinline__ void gemm_body(
    const float* __restrict__ A, const float* __restrict__ BT,
    float* __restrict__ C, int N, int K, int m0, int n0, int epi,
    const float* __restrict__ cvec, float* gsm) {
  const int tid = threadIdx.x;
  const int wid = tid >> 5;
  const int lane = tid & 31;
  const int wm = wid & 3;
  const int wn = wid >> 2;
  const int lg = lane >> 2;
  const int lt = lane & 3;
  const int rA = lane & 15;
  const int kaddA = ((lane >> 4) << 2);
  const int rB = ((lane >> 4) << 3) + (lane & 7);
  const int kaddB = (((lane >> 3) & 1) << 2);

  float acc[2][8][4];
#pragma unroll
  for (int i = 0; i < 2; ++i) {
#pragma unroll
    for (int j = 0; j < 8; ++j) {
#pragma unroll
      for (int t = 0; t < 4; ++t) { acc[i][j][t] = 0.f; }
    }
  }

  const int KT = K / 16;
  gemm_prefetch(A, BT, gsm + 0 * STAGE_F, tid, m0, n0, 0, K);
  cp_commit();
  gemm_prefetch(A, BT, gsm + 1 * STAGE_F, tid, m0, n0, 1, K);
  cp_commit();

  int st = 0;        // stage of tile kt
  int stn = 2;       // stage for tile kt+2
  for (int kt = 0; kt < KT; ++kt) {
    cp_wait1();
    __syncthreads();
    if (kt + 2 < KT) {
      gemm_prefetch(A, BT, gsm + stn * STAGE_F, tid, m0, n0, kt + 2, K);
      cp_commit();
    }
    float* Asb = gsm + st * STAGE_F;
    float* Bsb = Asb + 128 * LDA;

#pragma unroll
    for (int ks = 0; ks < 2; ++ks) {
      uint32_t a[2][4];
      uint32_t b[8][2];
#pragma unroll
      for (int mi = 0; mi < 2; ++mi) {
        ldsm4(a[mi], smem_u32(&Asb[(wm * 32 + mi * 16 + rA) * LDA + ks * 8 + kaddA]));
      }
#pragma unroll
      for (int j = 0; j < 4; ++j) {
        uint32_t r[4];
        ldsm4(r, smem_u32(&Bsb[(wn * 64 + j * 16 + rB) * LDA + ks * 8 + kaddB]));
        b[2 * j + 0][0] = r[0];
        b[2 * j + 0][1] = r[1];
        b[2 * j + 1][0] = r[2];
        b[2 * j + 1][1] = r[3];
      }
#pragma unroll
      for (int mi = 0; mi < 2; ++mi) {
#pragma unroll
        for (int nj = 0; nj < 8; ++nj) { mma_tf32(acc[mi][nj], a[mi], b[nj]); }
      }
    }
    st = (st == 2) ? 0 : st + 1;
    stn = (stn == 2) ? 0 : stn + 1;
  }

#pragma unroll
  for (int mi = 0; mi < 2; ++mi) {
    int r0 = m0 + wm * 32 + mi * 16 + lg;
#pragma unroll
    for (int nj = 0; nj < 8; ++nj) {
      int col = n0 + wn * 64 + nj * 8 + lt * 2;
#pragma unroll
      for (int half = 0; half < 2; ++half) {
        int row = r0 + half * 8;
        float v0 = acc[mi][nj][half * 2 + 0];
        float v1 = acc[mi][nj][half * 2 + 1];
        if (epi == 1) {
          v0 = rnd_tf32(tanhf(v0));
          v1 = rnd_tf32(tanhf(v1));
        } else if (epi == 2) {
          v0 = rnd_tf32(1.f / (1.f + __expf(-v0)) - 0.5f);
          v1 = rnd_tf32(1.f / (1.f + __expf(-v1)) - 0.5f);
        } else if (epi == 3) {
          v0 += cvec[col]; v1 += cvec[col + 1];
        }
        float2 v2 = make_float2(v0, v1);
        *(float2*)&C[(size_t)row * N + col] = v2;
      }
    }
  }
}

// Fused Q/K/V projection: grid.x = 12 column tiles (0-7 Q, 8-9 K, 10-11 V).
__global__ __launch_bounds__(256, 2)
void gemm_qkv(const float* __restrict__ x,
              const float* __restrict__ WqT, const float* __restrict__ WkT,
              const float* __restrict__ WvT,
              float* __restrict__ qb, float* __restrict__ kb, float* __restrict__ vp) {
  extern __shared__ float gsm[];
  const int xt = blockIdx.x;
  const int m0 = blockIdx.y * 128;
  const float* BT;
  float* C;
  int N, n0, epi;
  if (xt < 8) {
    BT = WqT; C = qb; N = H_N * QKB_N; n0 = xt * 128; epi = 1;
  } else if (xt < 10) {
    BT = WkT; C = kb; N = KV_N * QKB_N; n0 = (xt - 8) * 128; epi = 1;
  } else {
    BT = WvT; C = vp; N = KV_N * VB_N; n0 = (xt - 10) * 128; epi = 2;
  }
  gemm_body(x, BT, C, N, HID_N, m0, n0, epi, (const float*)0, gsm);
}

// Output projection: out = obd @ Wo + cvec
__global__ __launch_bounds__(256, 2)
void gemm_out(const float* __restrict__ obd, const float* __restrict__ WoT,
              float* __restrict__ out, const float* __restrict__ cvec) {
  extern __shared__ float gsm[];
  gemm_body(obd, WoT, out, HID_N, H_N * VB_N, blockIdx.y * 128, blockIdx.x * 128,
            3, cvec, gsm);
}

// ---------------------------------------------------------------------------
// Flash attention on tf32 mma, ldmatrix fragment loads, NO online max:
// scores are bounded (|s_raw| <= 64, exp(s/64) in [1/e, e]) so plain
// exponentials are safe. l accumulates unconditionally.
// ---------------------------------------------------------------------------
#define KS_P 68
#define P_P 68

__global__ __launch_bounds__(256)
void attn_mma_kernel(const int* __restrict__ amask,
                     const float* __restrict__ emb0,
                     const float* __restrict__ emb1) {
  extern __shared__ float smn[];
  float* Ks  = smn;                      // [64 kr][KS_P]
  float* Vst = Ks + 64 * KS_P;           // [64 vcol][KS_P] (kr contiguous)
  float* Pw  = Vst + 64 * KS_P;          // [8 warps][16][P_P]
  int*   Ms  = (int*)(Pw + 8 * 16 * P_P);

  const int qt = blockIdx.x;
  const int h  = blockIdx.y;
  const int b  = blockIdx.z;
  const int kv = h >> 2;
  const int tid = threadIdx.x;
  const int w = tid >> 5;
  const int lane = tid & 31;
  const int lg = lane >> 2;
  const int lt = lane & 3;
  const int q0 = qt * 128;
  const int r0 = q0 + w * 16 + lg;
  const int r1 = r0 + 8;
  const int rA = lane & 15;
  const int kaddA = ((lane >> 4) << 2);
  const int rB = ((lane >> 4) << 3) + (lane & 7);
  const int kaddB = (((lane >> 3) & 1) << 2);
  const float EXSC = 0.022542110013890053f;  // log2(e)/64

  uint32_t aq[8][4];
  {
    const float* Q0 = g_qb + (((size_t)b * S_N + r0) * H_N + h) * QKB_N;
    const float* Q1 = g_qb + (((size_t)b * S_N + r1) * H_N + h) * QKB_N;
#pragma unroll
    for (int ks = 0; ks < 8; ++ks) {
      aq[ks][0] = __float_as_uint(Q0[ks * 8 + lt]);
      aq[ks][1] = __float_as_uint(Q1[ks * 8 + lt]);
      aq[ks][2] = __float_as_uint(Q0[ks * 8 + lt + 4]);
      aq[ks][3] = __float_as_uint(Q1[ks * 8 + lt + 4]);
    }
  }

  float acc[8][4];
#pragma unroll
  for (int nj = 0; nj < 8; ++nj) {
#pragma unroll
    for (int t = 0; t < 4; ++t) { acc[nj][t] = 0.f; }
  }
  float l0 = 0.f, l1 = 0.f;

  float* Pme = Pw + w * 16 * P_P;

  const int nkt = 2 * qt + 2;
  for (int kt = 0; kt < nkt; ++kt) {
    const int k0 = kt * 64;
    __syncthreads();
#pragma unroll
    for (int it = 0; it < 2; ++it) {
      int c = tid + it * 256;
      int krow = c >> 3;
      int d0 = (c & 7) * 8;
      size_t base = (((size_t)b * S_N + k0 + krow) * KV_N + kv) * QKB_N + d0;
      float4 ka = *(const float4*)&g_kb[base];
      float4 kb4 = *(const float4*)&g_kb[base + 4];
      *(float4*)&Ks[krow * KS_P + d0] = ka;
      *(float4*)&Ks[krow * KS_P + d0 + 4] = kb4;
    }
#pragma unroll
    for (int it = 0; it < 4; ++it) {
      int c = tid + it * 256;
      int vcol = c & 63;
      int kc4 = (c >> 6) << 2;
      float4 vv;
      size_t base = (((size_t)b * S_N + k0 + kc4) * KV_N + kv) * VB_N + vcol;
      vv.x = g_vp[base];
      vv.y = g_vp[base + (size_t)KV_N * VB_N];
      vv.z = g_vp[base + (size_t)2 * KV_N * VB_N];
      vv.w = g_vp[base + (size_t)3 * KV_N * VB_N];
      *(float4*)&Vst[vcol * KS_P + kc4] = vv;
    }
    if (tid < 64) { Ms[tid] = amask[b * S_N + k0 + tid]; }
    __syncthreads();

    // ---- S = Q @ K^T ----
    float s[8][4];
#pragma unroll
    for (int nj = 0; nj < 8; ++nj) {
#pragma unroll
      for (int t = 0; t < 4; ++t) { s[nj][t] = 0.f; }
    }
#pragma unroll
    for (int ks = 0; ks < 8; ++ks) {
#pragma unroll
      for (int j = 0; j < 4; ++j) {
        uint32_t r[4];
        ldsm4(r, smem_u32(&Ks[(j * 16 + rB) * KS_P + ks * 8 + kaddB]));
        mma_tf32(s[2 * j + 0], aq[ks], r + 0);
        mma_tf32(s[2 * j + 1], aq[ks], r + 2);
      }
    }

    // ---- probs = exp(s/64), masked -> 0 (no max needed: |s|<=64) ----
    float rs0 = 0.f, rs1 = 0.f;
#pragma unroll
    for (int nj = 0; nj < 8; ++nj) {
      int c0i = nj * 8 + lt * 2;
      int kc0 = k0 + c0i;
      int kc1 = kc0 + 1;
      bool mk0 = Ms[c0i] != 0;
      bool mk1 = Ms[c0i + 1] != 0;
      float p00 = (kc0 <= r0 && mk0) ? exp2f(s[nj][0] * EXSC) : 0.f;
      float p01 = (kc1 <= r0 && mk1) ? exp2f(s[nj][1] * EXSC) : 0.f;
      float p10 = (kc0 <= r1 && mk0) ? exp2f(s[nj][2] * EXSC) : 0.f;
      float p11 = (kc1 <= r1 && mk1) ? exp2f(s[nj][3] * EXSC) : 0.f;
      rs0 += p00 + p01;
      rs1 += p10 + p11;
      float2 q2a = make_float2(p00, p01);
      float2 q2b = make_float2(p10, p11);
      *(float2*)&Pme[lg * P_P + nj * 8 + lt * 2] = q2a;
      *(float2*)&Pme[(lg + 8) * P_P + nj * 8 + lt * 2] = q2b;
    }
    rs0 += __shfl_xor_sync(0xffffffffu, rs0, 1);
    rs0 += __shfl_xor_sync(0xffffffffu, rs0, 2);
    rs1 += __shfl_xor_sync(0xffffffffu, rs1, 1);
    rs1 += __shfl_xor_sync(0xffffffffu, rs1, 2);
    l0 += rs0;
    l1 += rs1;
    __syncwarp();

    // ---- O += P @ V' ----
#pragma unroll
    for (int ks = 0; ks < 8; ++ks) {
      uint32_t pr[4];
      ldsm4(pr, smem_u32(&Pme[rA * P_P + ks * 8 + kaddA]));
      uint32_t hi[4];
      hi[0] = f2tf32(__uint_as_float(pr[0]));
      hi[1] = f2tf32(__uint_as_float(pr[1]));
      hi[2] = f2tf32(__uint_as_float(pr[2]));
      hi[3] = f2tf32(__uint_as_float(pr[3]));
#pragma unroll
      for (int j = 0; j < 4; ++j) {
        uint32_t r[4];
        ldsm4(r, smem_u32(&Vst[(j * 16 + rB) * KS_P + ks * 8 + kaddB]));
        mma_tf32(acc[2 * j + 0], hi, r + 0);
        mma_tf32(acc[2 * j + 1], hi, r + 2);
      }
    }
  }

  // ---- epilogue: centered out-bits (rounded to tf32 for the next GEMM) ----
  float inv0 = 1.f / l0;
  float inv1 = 1.f / l1;
#pragma unroll
  for (int nj = 0; nj < 8; ++nj) {
    int vc = nj * 8 + lt * 2;
    float d0 = emb1[h * VB_N + vc] - emb0[h * VB_N + vc];
    float d1 = emb1[h * VB_N + vc + 1] - emb0[h * VB_N + vc + 1];
    float2 o0 = make_float2(rnd_tf32(acc[nj][0] * inv0 * d0),
                            rnd_tf32(acc[nj][1] * inv0 * d1));
    float2 o1 = make_float2(rnd_tf32(acc[nj][2] * inv1 * d0),
                            rnd_tf32(acc[nj][3] * inv1 * d1));
    *(float2*)&g_obd[(((size_t)b * S_N + r0) * H_N + h) * VB_N + vc] = o0;
    *(float2*)&g_obd[(((size_t)b * S_N + r1) * H_N + h) * VB_N + vc] = o1;
  }
}

// ---------------------------------------------------------------------------
extern "C" void kernel_launch(void* const* d_in, const int* in_sizes, int n_in,
                              void* d_out, int out_size) {
  const float* x  = (const float*)d_in[0];
  const int*   am = (const int*)d_in[1];
  const float* Wq = (const float*)d_in[2];
  const float* Wk = (const float*)d_in[3];
  const float* Wv = (const float*)d_in[4];
  const float* Wo = (const float*)d_in[5];
  const float* e0 = (const float*)d_in[6];
  const float* e1 = (const float*)d_in[7];
  float* out = (float*)d_out;

  float* qb;  float* kb;  float* vp;  float* obd;  float* cvec;
  float* xr;  float* wqt; float* wkt; float* wvt;  float* wot;
  cudaGetSymbolAddress((void**)&qb, g_qb);
  cudaGetSymbolAddress((void**)&kb, g_kb);
  cudaGetSymbolAddress((void**)&vp, g_vp);
  cudaGetSymbolAddress((void**)&obd, g_obd);
  cudaGetSymbolAddress((void**)&cvec, g_cvec);
  cudaGetSymbolAddress((void**)&xr, g_xr);
  cudaGetSymbolAddress((void**)&wqt, g_wqt);
  cudaGetSymbolAddress((void**)&wkt, g_wkt);
  cudaGetSymbolAddress((void**)&wvt, g_wvt);
  cudaGetSymbolAddress((void**)&wot, g_wot);

  const int M = MTOT;

  round_tf32_kernel<<<(M * HID_N / 4 + 255) / 256, 256>>>(x, xr, M * HID_N / 4);
  transpose_round_kernel<<<dim3((H_N * QKB_N) / 32, HID_N / 32), 256>>>(Wq, wqt, HID_N, H_N * QKB_N);
  transpose_round_kernel<<<dim3((KV_N * QKB_N) / 32, HID_N / 32), 256>>>(Wk, wkt, HID_N, KV_N * QKB_N);
  transpose_round_kernel<<<dim3((KV_N * VB_N) / 32, HID_N / 32), 256>>>(Wv, wvt, HID_N, KV_N * VB_N);
  transpose_round_kernel<<<dim3(HID_N / 32, (H_N * VB_N) / 32), 256>>>(Wo, wot, H_N * VB_N, HID_N);
  cvec_kernel<<<HID_N / 256, 256>>>(e0, e1, Wo);

  const size_t gsm_bytes = (size_t)3 * STAGE_F * sizeof(float);  // 61440
  cudaFuncSetAttribute(gemm_qkv, cudaFuncAttributeMaxDynamicSharedMemorySize, (int)gsm_bytes);
  cudaFuncSetAttribute(gemm_out, cudaFuncAttributeMaxDynamicSharedMemorySize, (int)gsm_bytes);

  gemm_qkv<<<dim3(12, M / 128), 256, gsm_bytes>>>(xr, wqt, wkt, wvt, qb, kb, vp);

  size_t asmem = (size_t)(64 * KS_P + 64 * KS_P + 8 * 16 * P_P) * sizeof(float)
               + 64 * sizeof(int);
  cudaFuncSetAttribute(attn_mma_kernel, cudaFuncAttributeMaxDynamicSharedMemorySize, (int)asmem);
  attn_mma_kernel<<<dim3(S_N / 128, H_N, B_N), 256, asmem>>>(am, e0, e1);

  gemm_out<<<dim3(HID_N / 128, M / 128), 256, gsm_bytes>>>(obd, wot, out, cvec);
}

// round 10
// speedup vs baseline: 4.3996x; 1.2414x over previous
#include <cuda_runtime.h>
#include <stdint.h>
#include <math.h>

#define B_N 2
#define S_N 2048
#define HID_N 2048
#define H_N 16
#define KV_N 4
#define QKB_N 64
#define VB_N 64
#define MTOT (B_N * S_N)

// ---- scratch (__device__ globals: allocation-free rule) ----
__device__ float g_qb[(size_t)MTOT * H_N * QKB_N];    // round(tanh(x@Wq))
__device__ float g_kb[(size_t)MTOT * KV_N * QKB_N];   // round(tanh(x@Wk))
__device__ float g_vp[(size_t)MTOT * KV_N * VB_N];    // round(sigm(x@Wv)-0.5)
__device__ float g_obd[(size_t)MTOT * H_N * VB_N];    // round((ctx-.5)*(e1-e0))
__device__ float g_cvec[HID_N];
__device__ float g_xr [(size_t)MTOT * HID_N];         // round(x)
__device__ float g_wqt[(size_t)(H_N * QKB_N) * HID_N];   // round(Wq^T) [N][K]
__device__ float g_wkt[(size_t)(KV_N * QKB_N) * HID_N];  // round(Wk^T)
__device__ float g_wvt[(size_t)(KV_N * VB_N) * HID_N];   // round(Wv^T)
__device__ float g_wot[(size_t)HID_N * (H_N * VB_N)];    // round(Wo^T)

// ---- helpers ----
__device__ __forceinline__ uint32_t smem_u32(const void* p) {
  return (uint32_t)__cvta_generic_to_shared(p);
}

__device__ __forceinline__ void cp16(uint32_t dst, const void* src) {
  asm volatile("cp.async.cg.shared.global [%0], [%1], 16;"
               : : "r"(dst), "l"(src) : "memory");
}

__device__ __forceinline__ void cp_commit() {
  asm volatile("cp.async.commit_group;" : : : "memory");
}

__device__ __forceinline__ void cp_waitg0() {
  asm volatile("cp.async.wait_group 0;" : : : "memory");
}
__device__ __forceinline__ void cp_waitg1() {
  asm volatile("cp.async.wait_group 1;" : : : "memory");
}

__device__ __forceinline__ uint32_t f2tf32(float v) {
  uint32_t r;
  asm("cvt.rna.tf32.f32 %0, %1;" : "=r"(r) : "f"(v));
  return r;
}

__device__ __forceinline__ float rnd_tf32(float v) {
  return __uint_as_float(f2tf32(v));
}

__device__ __forceinline__ void ldsm4(uint32_t* r, uint32_t a) {
  asm volatile("ldmatrix.sync.aligned.m8n8.x4.shared.b16 {%0,%1,%2,%3}, [%4];"
               : "=r"(r[0]), "=r"(r[1]), "=r"(r[2]), "=r"(r[3])
               : "r"(a));
}

__device__ __forceinline__ void mma_tf32(float* d, const uint32_t* a, const uint32_t* b) {
  asm volatile(
    "mma.sync.aligned.m16n8k8.row.col.f32.tf32.tf32.f32 "
    "{%0,%1,%2,%3}, {%4,%5,%6,%7}, {%8,%9}, {%0,%1,%2,%3};"
    : "+f"(d[0]), "+f"(d[1]), "+f"(d[2]), "+f"(d[3])
    : "r"(a[0]), "r"(a[1]), "r"(a[2]), "r"(a[3]), "r"(b[0]), "r"(b[1]));
}

// ---- fp32 -> tf32-rounded fp32 ----
__global__ void round_tf32_kernel(const float* __restrict__ in,
                                  float* __restrict__ out, int n4) {
  int i = blockIdx.x * blockDim.x + threadIdx.x;
  if (i < n4) {
    float4 v = ((const float4*)in)[i];
    v.x = rnd_tf32(v.x);
    v.y = rnd_tf32(v.y);
    v.z = rnd_tf32(v.z);
    v.w = rnd_tf32(v.w);
    ((float4*)out)[i] = v;
  }
}

// ---- transpose + round: out[n][k] = rnd(in[k][n]) ----
__global__ void transpose_round_kernel(const float* __restrict__ in,
                                       float* __restrict__ out, int K, int N) {
  __shared__ float t[32][33];
  const int tx = threadIdx.x & 31;
  const int ty = threadIdx.x >> 5;
  const int n0 = blockIdx.x * 32;
  const int k0 = blockIdx.y * 32;
#pragma unroll
  for (int i = 0; i < 4; ++i) {
    int k = k0 + ty + i * 8;
    t[ty + i * 8][tx] = in[(size_t)k * N + n0 + tx];
  }
  __syncthreads();
#pragma unroll
  for (int i = 0; i < 4; ++i) {
    int n = n0 + ty + i * 8;
    out[(size_t)n * K + k0 + tx] = rnd_tf32(t[tx][ty + i * 8]);
  }
}

// ---- cvec[n] = sum_k 0.5*(e0[k]+e1[k]) * Wo[k][n]; k-split x4 + reduce ----
__global__ void cvec_kernel(const float* __restrict__ e0, const float* __restrict__ e1,
                            const float* __restrict__ Wo) {
  __shared__ float part[4][64];
  const int tid = threadIdx.x;
  const int col = tid & 63;
  const int sl = tid >> 6;           // 0..3
  const int n = blockIdx.x * 64 + col;
  float s = 0.f;
  const int k0 = sl * 256;
  for (int k = k0; k < k0 + 256; ++k) {
    s = fmaf(0.5f * (e0[k] + e1[k]), Wo[(size_t)k * HID_N + n], s);
  }
  part[sl][col] = s;
  __syncthreads();
  if (sl == 0) {
    g_cvec[n] = part[0][col] + part[1][col] + part[2][col] + part[3][col];
  }
}

// ---------------------------------------------------------------------------
// TF32 GEMM: C[M,N] = epi(A[M,K] @ BT[N,K]^T). Operands tf32-pre-rounded.
// 128x128x32 tile, 256 threads, mma.m16n8k8, ldmatrix, 3-stage cp.async ring.
// Stage layout: A 128 rows x 128B, B 128 rows x 128B, XOR-chunk swizzle
// (16B chunk index ^ (row&7)) -> conflict-free without padding. 96KB dsmem.
// epi: 1=tanh+round, 2=sigmoid-0.5+round, 3=add cvec[col].
// ---------------------------------------------------------------------------
#define STG_B 32768u                   // bytes per stage (A 16K + B 16K)
#define GEMM_DSMEM (3 * 32768)

__device__ __forceinline__ void g_prefetch(
    const float* __restrict__ A, const float* __restrict__ BT,
    uint32_t sA, int tid, int m0, int n0, int kt, int K) {
#pragma unroll
  for (int it = 0; it < 4; ++it) {
    int c = tid + it * 256;
    int r = c >> 3;
    int ch = c & 7;
    cp16(sA + r * 128 + ((uint32_t)(ch ^ (r & 7)) << 4),
         A + (size_t)(m0 + r) * K + kt * 32 + ch * 4);
  }
#pragma unroll
  for (int it = 0; it < 4; ++it) {
    int c = tid + it * 256;
    int r = c >> 3;
    int ch = c & 7;
    cp16(sA + 16384u + r * 128 + ((uint32_t)(ch ^ (r & 7)) << 4),
         BT + (size_t)(n0 + r) * K + kt * 32 + ch * 4);
  }
}

__device__ __forceinline__ void gemm_body(
    const float* __restrict__ A, const float* __restrict__ BT,
    float* __restrict__ C, int N, int K, int m0, int n0, int epi,
    const float* __restrict__ cvec) {
  extern __shared__ float gsm[];
  const int tid = threadIdx.x;
  const int wid = tid >> 5;
  const int lane = tid & 31;
  const int wm = wid & 3;
  const int wn = wid >> 2;
  const int lg = lane >> 2;
  const int lt = lane & 3;
  const int rA = lane & 15;
  const int hiA = lane >> 4;               // chunk low bit for A frags
  const int rB = ((lane >> 4) << 3) + (lane & 7);
  const int hiB = (lane >> 3) & 1;         // chunk low bit for B frags
  const uint32_t sbase = smem_u32(gsm);

  float acc[2][8][4];
#pragma unroll
  for (int i = 0; i < 2; ++i) {
#pragma unroll
    for (int j = 0; j < 8; ++j) {
#pragma unroll
      for (int t = 0; t < 4; ++t) { acc[i][j][t] = 0.f; }
    }
  }

  const int KT = K / 32;
  g_prefetch(A, BT, sbase + 0 * STG_B, tid, m0, n0, 0, K);
  cp_commit();
  g_prefetch(A, BT, sbase + 1 * STG_B, tid, m0, n0, 1, K);
  cp_commit();

  for (int kt = 0; kt < KT; ++kt) {
    // commits so far = min(KT, kt+2); need tile kt done:
    if (kt < KT - 1) { cp_waitg1(); } else { cp_waitg0(); }
    __syncthreads();
    if (kt + 2 < KT) {
      // stage (kt+2)%3 == (kt-1)%3, all warps passed the sync above so its
      // readers (iter kt-1) are done.
      g_prefetch(A, BT, sbase + (uint32_t)((kt + 2) % 3) * STG_B, tid, m0, n0, kt + 2, K);
      cp_commit();
    }

    const uint32_t Ab = sbase + (uint32_t)(kt % 3) * STG_B;
    const uint32_t Bb = Ab + 16384u;
#pragma unroll
    for (int ks = 0; ks < 4; ++ks) {
      uint32_t a[2][4];
      uint32_t b[8][2];
#pragma unroll
      for (int mi = 0; mi < 2; ++mi) {
        int row = wm * 32 + mi * 16 + rA;
        uint32_t ch = (uint32_t)(((ks << 1) | hiA) ^ (row & 7));
        ldsm4(a[mi], Ab + row * 128 + (ch << 4));
      }
#pragma unroll
      for (int j = 0; j < 4; ++j) {
        int row = wn * 64 + j * 16 + rB;
        uint32_t ch = (uint32_t)(((ks << 1) | hiB) ^ (row & 7));
        uint32_t r[4];
        ldsm4(r, Bb + row * 128 + (ch << 4));
        b[2 * j + 0][0] = r[0];
        b[2 * j + 0][1] = r[1];
        b[2 * j + 1][0] = r[2];
        b[2 * j + 1][1] = r[3];
      }
#pragma unroll
      for (int mi = 0; mi < 2; ++mi) {
#pragma unroll
        for (int nj = 0; nj < 8; ++nj) { mma_tf32(acc[mi][nj], a[mi], b[nj]); }
      }
    }
    __syncthreads();
  }

#pragma unroll
  for (int mi = 0; mi < 2; ++mi) {
    int r0 = m0 + wm * 32 + mi * 16 + lg;
#pragma unroll
    for (int nj = 0; nj < 8; ++nj) {
      int col = n0 + wn * 64 + nj * 8 + lt * 2;
#pragma unroll
      for (int half = 0; half < 2; ++half) {
        int row = r0 + half * 8;
        float v0 = acc[mi][nj][half * 2 + 0];
        float v1 = acc[mi][nj][half * 2 + 1];
        if (epi == 1) {
          v0 = rnd_tf32(tanhf(v0));
          v1 = rnd_tf32(tanhf(v1));
        } else if (epi == 2) {
          v0 = rnd_tf32(1.f / (1.f + __expf(-v0)) - 0.5f);
          v1 = rnd_tf32(1.f / (1.f + __expf(-v1)) - 0.5f);
        } else if (epi == 3) {
          v0 += cvec[col]; v1 += cvec[col + 1];
        }
        float2 v2 = make_float2(v0, v1);
        *(float2*)&C[(size_t)row * N + col] = v2;
      }
    }
  }
}

// Fused Q/K/V projection: grid.x = 12 column tiles (0-7 Q, 8-9 K, 10-11 V).
__global__ __launch_bounds__(256, 2)
void gemm_qkv(const float* __restrict__ x,
              const float* __restrict__ WqT, const float* __restrict__ WkT,
              const float* __restrict__ WvT,
              float* __restrict__ qb, float* __restrict__ kb, float* __restrict__ vp) {
  const int xt = blockIdx.x;
  const int m0 = blockIdx.y * 128;
  const float* BT;
  float* C;
  int N, n0, epi;
  if (xt < 8) {
    BT = WqT; C = qb; N = H_N * QKB_N; n0 = xt * 128; epi = 1;
  } else if (xt < 10) {
    BT = WkT; C = kb; N = KV_N * QKB_N; n0 = (xt - 8) * 128; epi = 1;
  } else {
    BT = WvT; C = vp; N = KV_N * VB_N; n0 = (xt - 10) * 128; epi = 2;
  }
  gemm_body(x, BT, C, N, HID_N, m0, n0, epi, (const float*)0);
}

// Output projection: out = obd @ Wo + cvec
__global__ __launch_bounds__(256, 2)
void gemm_out(const float* __restrict__ obd, const float* __restrict__ WoT,
              float* __restrict__ out, const float* __restrict__ cvec) {
  gemm_body(obd, WoT, out, HID_N, H_N * VB_N, blockIdx.y * 128, blockIdx.x * 128,
            3, cvec);
}

// ---------------------------------------------------------------------------
// Flash attention on tf32 mma.sync (R8 structure). Heavy q-tiles dispatched
// FIRST (qt reversed) to balance the causal-work tail across waves.
// ---------------------------------------------------------------------------
#define KS_P 68
#define P_P 68

__global__ __launch_bounds__(256)
void attn_mma_kernel(const int* __restrict__ amask,
                     const float* __restrict__ emb0,
                     const float* __restrict__ emb1) {
  extern __shared__ float smn[];
  float* Ks  = smn;                      // [64 kr][KS_P]
  float* Vst = Ks + 64 * KS_P;           // [64 vcol][KS_P] (kr contiguous)
  float* Pw  = Vst + 64 * KS_P;          // [8 warps][16][P_P]
  int*   Ms  = (int*)(Pw + 8 * 16 * P_P);

  const int qt = (int)gridDim.x - 1 - (int)blockIdx.x;  // heavy tiles first
  const int h  = blockIdx.y;
  const int b  = blockIdx.z;
  const int kv = h >> 2;
  const int tid = threadIdx.x;
  const int w = tid >> 5;
  const int lane = tid & 31;
  const int lg = lane >> 2;
  const int lt = lane & 3;
  const int q0 = qt * 128;
  const int r0 = q0 + w * 16 + lg;
  const int r1 = r0 + 8;
  const int rA = lane & 15;
  const int kaddA = ((lane >> 4) << 2);
  const int rB = ((lane >> 4) << 3) + (lane & 7);
  const int kaddB = (((lane >> 3) & 1) << 2);
  const float EXSC = 0.022542110013890053f;  // log2(e)/64

  uint32_t aq[8][4];
  {
    const float* Q0 = g_qb + (((size_t)b * S_N + r0) * H_N + h) * QKB_N;
    const float* Q1 = g_qb + (((size_t)b * S_N + r1) * H_N + h) * QKB_N;
#pragma unroll
    for (int ks = 0; ks < 8; ++ks) {
      aq[ks][0] = __float_as_uint(Q0[ks * 8 + lt]);
      aq[ks][1] = __float_as_uint(Q1[ks * 8 + lt]);
      aq[ks][2] = __float_as_uint(Q0[ks * 8 + lt + 4]);
      aq[ks][3] = __float_as_uint(Q1[ks * 8 + lt + 4]);
    }
  }

  float acc[8][4];
#pragma unroll
  for (int nj = 0; nj < 8; ++nj) {
#pragma unroll
    for (int t = 0; t < 4; ++t) { acc[nj][t] = 0.f; }
  }
  float l0 = 0.f, l1 = 0.f;

  float* Pme = Pw + w * 16 * P_P;

  const int nkt = 2 * qt + 2;
  for (int kt = 0; kt < nkt; ++kt) {
    const int k0 = kt * 64;
    __syncthreads();
#pragma unroll
    for (int it = 0; it < 2; ++it) {
      int c = tid + it * 256;
      int krow = c >> 3;
      int d0 = (c & 7) * 8;
      size_t base = (((size_t)b * S_N + k0 + krow) * KV_N + kv) * QKB_N + d0;
      float4 ka = *(const float4*)&g_kb[base];
      float4 kb4 = *(const float4*)&g_kb[base + 4];
      *(float4*)&Ks[krow * KS_P + d0] = ka;
      *(float4*)&Ks[krow * KS_P + d0 + 4] = kb4;
    }
#pragma unroll
    for (int it = 0; it < 4; ++it) {
      int c = tid + it * 256;
      int vcol = c & 63;
      int kc4 = (c >> 6) << 2;
      float4 vv;
      size_t base = (((size_t)b * S_N + k0 + kc4) * KV_N + kv) * VB_N + vcol;
      vv.x = g_vp[base];
      vv.y = g_vp[base + (size_t)KV_N * VB_N];
      vv.z = g_vp[base + (size_t)2 * KV_N * VB_N];
      vv.w = g_vp[base + (size_t)3 * KV_N * VB_N];
      *(float4*)&Vst[vcol * KS_P + kc4] = vv;
    }
    if (tid < 64) { Ms[tid] = amask[b * S_N + k0 + tid]; }
    __syncthreads();

    float s[8][4];
#pragma unroll
    for (int nj = 0; nj < 8; ++nj) {
#pragma unroll
      for (int t = 0; t < 4; ++t) { s[nj][t] = 0.f; }
    }
#pragma unroll
    for (int ks = 0; ks < 8; ++ks) {
#pragma unroll
      for (int j = 0; j < 4; ++j) {
        uint32_t r[4];
        ldsm4(r, smem_u32(&Ks[(j * 16 + rB) * KS_P + ks * 8 + kaddB]));
        mma_tf32(s[2 * j + 0], aq[ks], r + 0);
        mma_tf32(s[2 * j + 1], aq[ks], r + 2);
      }
    }

    float rs0 = 0.f, rs1 = 0.f;
#pragma unroll
    for (int nj = 0; nj < 8; ++nj) {
      int c0i = nj * 8 + lt * 2;
      int kc0 = k0 + c0i;
      int kc1 = kc0 + 1;
      bool mk0 = Ms[c0i] != 0;
      bool mk1 = Ms[c0i + 1] != 0;
      float p00 = (kc0 <= r0 && mk0) ? exp2f(s[nj][0] * EXSC) : 0.f;
      float p01 = (kc1 <= r0 && mk1) ? exp2f(s[nj][1] * EXSC) : 0.f;
      float p10 = (kc0 <= r1 && mk0) ? exp2f(s[nj][2] * EXSC) : 0.f;
      float p11 = (kc1 <= r1 && mk1) ? exp2f(s[nj][3] * EXSC) : 0.f;
      rs0 += p00 + p01;
      rs1 += p10 + p11;
      float2 q2a = make_float2(p00, p01);
      float2 q2b = make_float2(p10, p11);
      *(float2*)&Pme[lg * P_P + nj * 8 + lt * 2] = q2a;
      *(float2*)&Pme[(lg + 8) * P_P + nj * 8 + lt * 2] = q2b;
    }
    rs0 += __shfl_xor_sync(0xffffffffu, rs0, 1);
    rs0 += __shfl_xor_sync(0xffffffffu, rs0, 2);
    rs1 += __shfl_xor_sync(0xffffffffu, rs1, 1);
    rs1 += __shfl_xor_sync(0xffffffffu, rs1, 2);
    l0 += rs0;
    l1 += rs1;
    __syncwarp();

#pragma unroll
    for (int ks = 0; ks < 8; ++ks) {
      uint32_t pr[4];
      ldsm4(pr, smem_u32(&Pme[rA * P_P + ks * 8 + kaddA]));
      uint32_t hi[4];
      hi[0] = f2tf32(__uint_as_float(pr[0]));
      hi[1] = f2tf32(__uint_as_float(pr[1]));
      hi[2] = f2tf32(__uint_as_float(pr[2]));
      hi[3] = f2tf32(__uint_as_float(pr[3]));
#pragma unroll
      for (int j = 0; j < 4; ++j) {
        uint32_t r[4];
        ldsm4(r, smem_u32(&Vst[(j * 16 + rB) * KS_P + ks * 8 + kaddB]));
        mma_tf32(acc[2 * j + 0], hi, r + 0);
        mma_tf32(acc[2 * j + 1], hi, r + 2);
      }
    }
  }

  float inv0 = 1.f / l0;
  float inv1 = 1.f / l1;
#pragma unroll
  for (int nj = 0; nj < 8; ++nj) {
    int vc = nj * 8 + lt * 2;
    float d0 = emb1[h * VB_N + vc] - emb0[h * VB_N + vc];
    float d1 = emb1[h * VB_N + vc + 1] - emb0[h * VB_N + vc + 1];
    float2 o0 = make_float2(rnd_tf32(acc[nj][0] * inv0 * d0),
                            rnd_tf32(acc[nj][1] * inv0 * d1));
    float2 o1 = make_float2(rnd_tf32(acc[nj][2] * inv1 * d0),
                            rnd_tf32(acc[nj][3] * inv1 * d1));
    *(float2*)&g_obd[(((size_t)b * S_N + r0) * H_N + h) * VB_N + vc] = o0;
    *(float2*)&g_obd[(((size_t)b * S_N + r1) * H_N + h) * VB_N + vc] = o1;
  }
}

// ---------------------------------------------------------------------------
extern "C" void kernel_launch(void* const* d_in, const int* in_sizes, int n_in,
                              void* d_out, int out_size) {
  const float* x  = (const float*)d_in[0];
  const int*   am = (const int*)d_in[1];
  const float* Wq = (const float*)d_in[2];
  const float* Wk = (const float*)d_in[3];
  const float* Wv = (const float*)d_in[4];
  const float* Wo = (const float*)d_in[5];
  const float* e0 = (const float*)d_in[6];
  const float* e1 = (const float*)d_in[7];
  float* out = (float*)d_out;

  float* qb;  float* kb;  float* vp;  float* obd;  float* cvec;
  float* xr;  float* wqt; float* wkt; float* wvt;  float* wot;
  cudaGetSymbolAddress((void**)&qb, g_qb);
  cudaGetSymbolAddress((void**)&kb, g_kb);
  cudaGetSymbolAddress((void**)&vp, g_vp);
  cudaGetSymbolAddress((void**)&obd, g_obd);
  cudaGetSymbolAddress((void**)&cvec, g_cvec);
  cudaGetSymbolAddress((void**)&xr, g_xr);
  cudaGetSymbolAddress((void**)&wqt, g_wqt);
  cudaGetSymbolAddress((void**)&wkt, g_wkt);
  cudaGetSymbolAddress((void**)&wvt, g_wvt);
  cudaGetSymbolAddress((void**)&wot, g_wot);

  const int M = MTOT;

  round_tf32_kernel<<<(M * HID_N / 4 + 255) / 256, 256>>>(x, xr, M * HID_N / 4);
  transpose_round_kernel<<<dim3((H_N * QKB_N) / 32, HID_N / 32), 256>>>(Wq, wqt, HID_N, H_N * QKB_N);
  transpose_round_kernel<<<dim3((KV_N * QKB_N) / 32, HID_N / 32), 256>>>(Wk, wkt, HID_N, KV_N * QKB_N);
  transpose_round_kernel<<<dim3((KV_N * VB_N) / 32, HID_N / 32), 256>>>(Wv, wvt, HID_N, KV_N * VB_N);
  transpose_round_kernel<<<dim3(HID_N / 32, (H_N * VB_N) / 32), 256>>>(Wo, wot, H_N * VB_N, HID_N);
  cvec_kernel<<<HID_N / 64, 256>>>(e0, e1, Wo);

  cudaFuncSetAttribute(gemm_qkv, cudaFuncAttributeMaxDynamicSharedMemorySize, GEMM_DSMEM);
  cudaFuncSetAttribute(gemm_out, cudaFuncAttributeMaxDynamicSharedMemorySize, GEMM_DSMEM);

  gemm_qkv<<<dim3(12, M / 128), 256, GEMM_DSMEM>>>(xr, wqt, wkt, wvt, qb, kb, vp);

  size_t asmem = (size_t)(64 * KS_P + 64 * KS_P + 8 * 16 * P_P) * sizeof(float)
               + 64 * sizeof(int);
  cudaFuncSetAttribute(attn_mma_kernel, cudaFuncAttributeMaxDynamicSharedMemorySize, (int)asmem);
  attn_mma_kernel<<<dim3(S_N / 128, H_N, B_N), 256, asmem>>>(am, e0, e1);

  gemm_out<<<dim3(HID_N / 128, M / 128), 256, GEMM_DSMEM>>>(obd, wot, out, cvec);
}